// round 12
// baseline (speedup 1.0000x reference)
#include <cuda_runtime.h>
#include <cuda_fp16.h>
#include <math.h>
#include <stdint.h>

#define BATCH 2
#define SEQ   2048
#define EMB   2048
#define HEADS 16
#define HDIM  128
#define THREE_E 6144
#define MROWS (BATCH*SEQ)     // 4096
#define NBH   (BATCH*HEADS)   // 32

// ---------------- scratch (__device__ globals; no cudaMalloc) ----------------
__device__ float g_qkv[(size_t)MROWS * THREE_E];                 // fp32 QKV
__device__ __half g_x16[(size_t)MROWS * EMB];                    // x plain fp16
__device__ __half g_w16[(size_t)THREE_E * EMB];                  // wqkv plain fp16
__device__ __half g_o16w[(size_t)EMB * EMB];                     // out_w plain fp16
__device__ __half g_qp[(size_t)NBH*SEQ*HDIM];                    // Q plain fp16
__device__ __half g_khh[(size_t)NBH*SEQ*HDIM], g_kll[(size_t)NBH*SEQ*HDIM];
__device__ __half g_vp[(size_t)NBH*SEQ*HDIM];                    // V plain fp16
__device__ __half g_c16[(size_t)MROWS * EMB];                    // ctx plain fp16

// ---------------- PTX helpers ----------------
__device__ __forceinline__ uint32_t smem_u32(const void* p) {
    uint32_t a;
    asm("{ .reg .u64 t; cvta.to.shared.u64 t, %1; cvt.u32.u64 %0, t; }"
        : "=r"(a) : "l"(p));
    return a;
}
__device__ __forceinline__ uint32_t cvt_plain_h(float f0, float f1) {
    uint32_t h;
    asm("cvt.rn.f16x2.f32 %0, %1, %2;" : "=r"(h) : "f"(f1), "f"(f0));
    return h;
}
#define LDMX4(r0, r1, r2, r3, addr) \
    asm volatile("ldmatrix.sync.aligned.m8n8.x4.shared.b16 {%0,%1,%2,%3}, [%4];" \
        : "=r"(r0), "=r"(r1), "=r"(r2), "=r"(r3) : "r"(addr))
#define LDMT4(r0, r1, r2, r3, addr) \
    asm volatile("ldmatrix.sync.aligned.m8n8.x4.trans.shared.b16 {%0,%1,%2,%3}, [%4];" \
        : "=r"(r0), "=r"(r1), "=r"(r2), "=r"(r3) : "r"(addr))
#define MMA16816(d, a, b0, b1) \
    asm volatile("mma.sync.aligned.m16n8k16.row.col.f32.f16.f16.f32 " \
        "{%0,%1,%2,%3}, {%4,%5,%6,%7}, {%8,%9}, {%0,%1,%2,%3};" \
        : "+f"((d)[0]), "+f"((d)[1]), "+f"((d)[2]), "+f"((d)[3]) \
        : "r"((a)[0]), "r"((a)[1]), "r"((a)[2]), "r"((a)[3]), "r"(b0), "r"(b1))
#define CP16(dst, src) \
    asm volatile("cp.async.cg.shared.global [%0], [%1], 16;" :: "r"(dst), "l"(src))
#define CPCOMMIT() asm volatile("cp.async.commit_group;" ::: "memory")
#define CPWAIT0()  asm volatile("cp.async.wait_group 0;" ::: "memory")
#define CPWAIT1()  asm volatile("cp.async.wait_group 1;" ::: "memory")

// ---------------------------------------------------------------------------
// Prep kernels
// ---------------------------------------------------------------------------
__global__ void cvt_f32_h(const float4* __restrict__ in,
                          uint2* __restrict__ o16, int n4)
{
    int i = blockIdx.x * blockDim.x + threadIdx.x;
    if (i >= n4) return;
    float4 v = in[i];
    o16[i] = make_uint2(cvt_plain_h(v.x, v.y), cvt_plain_h(v.z, v.w));
}

// ---------------------------------------------------------------------------
// fp16 single-product tensor GEMM: C[M,N] = A[M,K] @ B[N,K]^T + bias
// BM=BN=128, BK=64, 256 threads = 8 warps (2m x 4n). 3-stage, 2 CTAs/SM.
// ---------------------------------------------------------------------------
#define LDS 72                       // 64 fp16 data + 8 pad per row (144 B)
#define A_SB (128 * LDS * 2)         // 18432 B
#define STAGE_SB (2 * A_SB)          // 36864 B (A + B)
#define GEMM_SMEM (3 * STAGE_SB)     // 110592 B  -> 2 CTAs/SM

__device__ __forceinline__ void gemm_issue(
    const __half* A, const __half* B,
    uint32_t sbase, int m0, int n0, int K, int cc, int tid)
{
    const uint32_t stg = sbase + (uint32_t)(cc % 3) * STAGE_SB;
    const int k0 = cc * 64;
#pragma unroll
    for (int i = 0; i < 4; i++) {
        int c = tid + i * 256;       // 0..1023
        int r = c >> 3, sg = c & 7;
        uint32_t dof = (uint32_t)(r * 144 + sg * 16);
        size_t ao = (size_t)(m0 + r) * K + k0 + sg * 8;
        size_t bo = (size_t)(n0 + r) * K + k0 + sg * 8;
        CP16(stg + dof, (const char*)(A + ao));
        CP16(stg + A_SB + dof, (const char*)(B + bo));
    }
    CPCOMMIT();
}

__global__ __launch_bounds__(256, 2) void gemm_fp16(
    const __half* __restrict__ A, const __half* __restrict__ B,
    const float* __restrict__ bias, float* __restrict__ C, int N, int K)
{
    extern __shared__ char dsm[];
    __shared__ float sBias[128];

    const int tid  = threadIdx.x;
    const int lane = tid & 31;
    const int wid  = tid >> 5;
    const int wm   = wid >> 2;
    const int wn   = wid & 3;
    const int m0 = blockIdx.y * 128, n0 = blockIdx.x * 128;
    const uint32_t sbase = smem_u32(dsm);

    if (tid < 128) sBias[tid] = bias[n0 + tid];

    const int NCH = K >> 6;
    gemm_issue(A, B, sbase, m0, n0, K, 0, tid);
    gemm_issue(A, B, sbase, m0, n0, K, 1, tid);

    float acc[4][4][4];
#pragma unroll
    for (int mt = 0; mt < 4; mt++)
#pragma unroll
        for (int nt = 0; nt < 4; nt++)
#pragma unroll
            for (int r = 0; r < 4; r++) acc[mt][nt][r] = 0.0f;

    const uint32_t a_row  = (uint32_t)(wm * 64 + (lane & 15));
    const uint32_t a_koff = (uint32_t)((lane >> 4) * 8);
    const uint32_t b_row  = (uint32_t)(wn * 32 + (lane & 7) + ((lane >> 4) << 3));
    const uint32_t b_koff = (uint32_t)(((lane >> 3) & 1) * 8);

    for (int c = 0; c < NCH; c++) {
        CPWAIT1();
        __syncthreads();
        if (c + 2 < NCH) gemm_issue(A, B, sbase, m0, n0, K, c + 2, tid);
        else CPCOMMIT();

        const uint32_t stg = sbase + (uint32_t)(c % 3) * STAGE_SB;
#pragma unroll
        for (int ks = 0; ks < 4; ks++) {
            const uint32_t kofs = (uint32_t)(ks * 16);
            uint32_t a[4][4];
#pragma unroll
            for (int mt = 0; mt < 4; mt++) {
                uint32_t adr = stg + ((a_row + mt * 16) * LDS + kofs + a_koff) * 2;
                LDMX4(a[mt][0], a[mt][1], a[mt][2], a[mt][3], adr);
            }
            uint32_t b[2][4];
#pragma unroll
            for (int p = 0; p < 2; p++) {
                uint32_t adr = stg + A_SB
                             + ((b_row + p * 16) * LDS + kofs + b_koff) * 2;
                LDMX4(b[p][0], b[p][1], b[p][2], b[p][3], adr);
            }
#pragma unroll
            for (int mt = 0; mt < 4; mt++)
#pragma unroll
                for (int nt = 0; nt < 4; nt++) {
                    const int p = nt >> 1, hh = (nt & 1) * 2;
                    MMA16816(acc[mt][nt], a[mt], b[p][hh], b[p][hh + 1]);
                }
        }
    }

    const int erow = wm * 64 + (lane >> 2);
    const int ecol = wn * 32 + (lane & 3) * 2;
#pragma unroll
    for (int mt = 0; mt < 4; mt++) {
#pragma unroll
        for (int nt = 0; nt < 4; nt++) {
            const int cc = ecol + nt * 8;
            const float b0 = sBias[cc], b1 = sBias[cc + 1];
            float* p0 = C + (size_t)(m0 + erow + mt * 16) * N + n0 + cc;
            float* p1 = C + (size_t)(m0 + erow + mt * 16 + 8) * N + n0 + cc;
            float2 v0 = {acc[mt][nt][0] + b0, acc[mt][nt][1] + b1};
            float2 v1 = {acc[mt][nt][2] + b0, acc[mt][nt][3] + b1};
            *(float2*)p0 = v0;
            *(float2*)p1 = v1;
        }
    }
}

// ---------------------------------------------------------------------------
// RoPE + layout: Q plain fp16 (scaled), K hi/lo, V plain
// ---------------------------------------------------------------------------
__device__ __forceinline__ void split1h(float x, __half* ph, __half* pl) {
    __half h = __float2half_rn(x);
    *ph = h;
    *pl = __float2half_rn(x - __half2float(h));
}

__global__ __launch_bounds__(256) void rope_split(
    const float* __restrict__ qkv,
    __half* __restrict__ Qp,
    __half* __restrict__ Kh, __half* __restrict__ Kl,
    __half* __restrict__ Vp)
{
    int idx = blockIdx.x * blockDim.x + threadIdx.x;   // NBH*SEQ*64
    if (idx >= NBH * SEQ * 64) return;
    int j  = idx & 63;
    int s  = (idx >> 6) & (SEQ - 1);
    int bh = idx >> 17;
    int b = bh >> 4, h = bh & 15;

    size_t base = ((size_t)(b * SEQ + s) * 3) * EMB + h * HDIM;
    size_t dst  = ((size_t)bh * SEQ + s) * HDIM + j;
    const float scale = 0.08838834764831845f;

    float inv = powf(10000.0f, -(float)j / 64.0f);
    float ang = (float)s * inv;
    float sn, cs;
    sincosf(ang, &sn, &cs);

    float q1 = qkv[base + j], q2 = qkv[base + 64 + j];
    Qp[dst]      = __float2half_rn((q1 * cs - q2 * sn) * scale);
    Qp[dst + 64] = __float2half_rn((q1 * sn + q2 * cs) * scale);
    float k1 = qkv[base + EMB + j], k2 = qkv[base + EMB + 64 + j];
    split1h(k1 * cs - k2 * sn, Kh + dst, Kl + dst);
    split1h(k1 * sn + k2 * cs, Kh + dst + 64, Kl + dst + 64);
    Vp[dst]      = __float2half_rn(qkv[base + 2 * EMB + j]);
    Vp[dst + 64] = __float2half_rn(qkv[base + 2 * EMB + 64 + j]);
}

// ---------------------------------------------------------------------------
// Flash attention: Q block 128 rows, 256 threads (8 warps x 16 q-rows),
// KV tiles 64, K hi/lo scores, V plain, causal. 2 CTAs/SM.
// smem: Q (128 rows) + Kh + Kl + V (64 rows each)
// ---------------------------------------------------------------------------
#define FL_STRIDE_B 272                  // 136 fp16 per smem row
#define FL_TILE (64 * FL_STRIDE_B)       // 17408 B (64-row tile)
#define FL_Q_SB (128 * FL_STRIDE_B)      // 34816 B (128-row Q tile)
#define FLASH_SMEM (FL_Q_SB + 3 * FL_TILE)   // 87040 B -> 2 CTAs/SM

__global__ __launch_bounds__(256, 2) void flash_mma(
    const __half* __restrict__ Qp,
    const __half* __restrict__ Kh, const __half* __restrict__ Kl,
    const __half* __restrict__ Vp,
    __half* __restrict__ ctx)
{
    extern __shared__ char fsm[];
    const int qt = gridDim.x - 1 - blockIdx.x;   // heavy tiles first
    const int bh = blockIdx.y;
    const int tid = threadIdx.x, lane = tid & 31, w = tid >> 5;  // w: 0..7
    const int q0 = qt * 128;
    const uint32_t sb = smem_u32(fsm);

    // Load Q block: 128 rows x 128 fp16 = 2048 uint4
    {
        const size_t qo = ((size_t)bh * SEQ + q0) * HDIM;
#pragma unroll
        for (int i = 0; i < 8; i++) {
            int c = tid + i * 256;
            int r = c >> 4, sg = c & 15;
            *(uint4*)(fsm + r * FL_STRIDE_B + sg * 16) =
                *(const uint4*)(Qp + qo + r * HDIM + sg * 8);
        }
    }

    float m0v = -1e30f, m1v = -1e30f, l0v = 0.0f, l1v = 0.0f;
    float o[16][4];
#pragma unroll
    for (int nt = 0; nt < 16; nt++)
#pragma unroll
        for (int r = 0; r < 4; r++) o[nt][r] = 0.0f;

    const uint32_t a_row  = (uint32_t)(w * 16 + (lane & 15));   // 0..127
    const uint32_t a_koff = (uint32_t)((lane >> 4) * 8);
    const uint32_t b_row  = (uint32_t)((lane & 7) + ((lane >> 4) << 3));
    const uint32_t b_koff = (uint32_t)(((lane >> 3) & 1) * 8);
    const uint32_t v_row  = (uint32_t)(lane & 15);
    const uint32_t v_coff = (uint32_t)((lane >> 4) * 8);

    const int nkt = 2 * qt + 2;   // KV tiles needed for this Q block
    for (int kt = 0; kt < nkt; kt++) {
        __syncthreads();

        const size_t ko = ((size_t)bh * SEQ + kt * 64) * HDIM;
        // K hi/lo: 64 rows x 16 segs = 1024 uint4 -> 4 iters of 256 thr
#pragma unroll
        for (int i = 0; i < 4; i++) {
            int c = tid + i * 256;
            int r = c >> 4, sg = c & 15;
            uint32_t dof = (uint32_t)(r * FL_STRIDE_B + sg * 16);
            size_t so = ko + r * HDIM + sg * 8;
            CP16(sb + FL_Q_SB + dof, (const char*)(Kh + so));
            CP16(sb + FL_Q_SB + FL_TILE + dof, (const char*)(Kl + so));
        }
        CPCOMMIT();
#pragma unroll
        for (int i = 0; i < 4; i++) {
            int c = tid + i * 256;
            int r = c >> 4, sg = c & 15;
            uint32_t dof = (uint32_t)(r * FL_STRIDE_B + sg * 16);
            size_t so = ko + r * HDIM + sg * 8;
            CP16(sb + FL_Q_SB + 2 * FL_TILE + dof, (const char*)(Vp + so));
        }
        CPCOMMIT();

        CPWAIT1();
        __syncthreads();

        float s[8][4];
#pragma unroll
        for (int nt = 0; nt < 8; nt++)
#pragma unroll
            for (int r = 0; r < 4; r++) s[nt][r] = 0.0f;

#pragma unroll
        for (int ks = 0; ks < 8; ks++) {
            uint32_t q[4];
            uint32_t qadr = sb + a_row * FL_STRIDE_B + (ks * 16 + a_koff) * 2;
            LDMX4(q[0], q[1], q[2], q[3], qadr);
            uint32_t khf[4][4], klf[4][4];
#pragma unroll
            for (int np = 0; np < 4; np++) {
                uint32_t kadr = sb + FL_Q_SB
                              + (np * 16 + b_row) * FL_STRIDE_B
                              + (ks * 16 + b_koff) * 2;
                LDMX4(khf[np][0], khf[np][1], khf[np][2], khf[np][3], kadr);
                LDMX4(klf[np][0], klf[np][1], klf[np][2], klf[np][3], kadr + FL_TILE);
            }
#pragma unroll
            for (int np = 0; np < 4; np++) {
                MMA16816(s[2*np],   q, khf[np][0], khf[np][1]);
                MMA16816(s[2*np+1], q, khf[np][2], khf[np][3]);
            }
#pragma unroll
            for (int np = 0; np < 4; np++) {
                MMA16816(s[2*np],   q, klf[np][0], klf[np][1]);
                MMA16816(s[2*np+1], q, klf[np][2], klf[np][3]);
            }
        }

        // causal mask on the last two tiles (kt >= 2*qt)
        if (kt >= 2 * qt) {
            const int r0 = q0 + w * 16 + (lane >> 2);
            const int r1 = r0 + 8;
            const int c0 = kt * 64;
#pragma unroll
            for (int nt = 0; nt < 8; nt++) {
                const int cb = c0 + nt * 8 + (lane & 3) * 2;
                if (cb     > r0) s[nt][0] = -1e30f;
                if (cb + 1 > r0) s[nt][1] = -1e30f;
                if (cb     > r1) s[nt][2] = -1e30f;
                if (cb + 1 > r1) s[nt][3] = -1e30f;
            }
        }

        float mx0 = -1e30f, mx1 = -1e30f;
#pragma unroll
        for (int nt = 0; nt < 8; nt++) {
            mx0 = fmaxf(mx0, fmaxf(s[nt][0], s[nt][1]));
            mx1 = fmaxf(mx1, fmaxf(s[nt][2], s[nt][3]));
        }
        mx0 = fmaxf(mx0, __shfl_xor_sync(0xffffffffu, mx0, 1));
        mx0 = fmaxf(mx0, __shfl_xor_sync(0xffffffffu, mx0, 2));
        mx1 = fmaxf(mx1, __shfl_xor_sync(0xffffffffu, mx1, 1));
        mx1 = fmaxf(mx1, __shfl_xor_sync(0xffffffffu, mx1, 2));

        float mn0 = fmaxf(m0v, mx0), mn1 = fmaxf(m1v, mx1);
        float sf0 = __expf(m0v - mn0), sf1 = __expf(m1v - mn1);
        m0v = mn0; m1v = mn1;

        float ls0 = 0.0f, ls1 = 0.0f;
#pragma unroll
        for (int nt = 0; nt < 8; nt++) {
            s[nt][0] = __expf(s[nt][0] - mn0); ls0 += s[nt][0];
            s[nt][1] = __expf(s[nt][1] - mn0); ls0 += s[nt][1];
            s[nt][2] = __expf(s[nt][2] - mn1); ls1 += s[nt][2];
            s[nt][3] = __expf(s[nt][3] - mn1); ls1 += s[nt][3];
        }
        ls0 += __shfl_xor_sync(0xffffffffu, ls0, 1);
        ls0 += __shfl_xor_sync(0xffffffffu, ls0, 2);
        ls1 += __shfl_xor_sync(0xffffffffu, ls1, 1);
        ls1 += __shfl_xor_sync(0xffffffffu, ls1, 2);
        l0v = l0v * sf0 + ls0;
        l1v = l1v * sf1 + ls1;
#pragma unroll
        for (int nt = 0; nt < 16; nt++) {
            o[nt][0] *= sf0; o[nt][1] *= sf0;
            o[nt][2] *= sf1; o[nt][3] *= sf1;
        }

        // P fragments (plain fp16)
        uint32_t ph[4][4];
#pragma unroll
        for (int k2 = 0; k2 < 4; k2++) {
            ph[k2][0] = cvt_plain_h(s[2*k2][0],   s[2*k2][1]);
            ph[k2][1] = cvt_plain_h(s[2*k2][2],   s[2*k2][3]);
            ph[k2][2] = cvt_plain_h(s[2*k2+1][0], s[2*k2+1][1]);
            ph[k2][3] = cvt_plain_h(s[2*k2+1][2], s[2*k2+1][3]);
        }

        CPWAIT0();
        __syncthreads();

        // O += P V
#pragma unroll
        for (int k2 = 0; k2 < 4; k2++) {
#pragma unroll
            for (int npp = 0; npp < 4; npp++) {
                const int np0 = 2 * npp, np1 = 2 * npp + 1;
                uint32_t vh0[4], vh1[4];
                uint32_t va0 = sb + FL_Q_SB + 2 * FL_TILE
                             + (k2 * 16 + v_row) * FL_STRIDE_B
                             + (np0 * 16 + v_coff) * 2;
                uint32_t va1 = va0 + 32;
                LDMT4(vh0[0], vh0[1], vh0[2], vh0[3], va0);
                LDMT4(vh1[0], vh1[1], vh1[2], vh1[3], va1);
                MMA16816(o[2*np0],   ph[k2], vh0[0], vh0[1]);
                MMA16816(o[2*np0+1], ph[k2], vh0[2], vh0[3]);
                MMA16816(o[2*np1],   ph[k2], vh1[0], vh1[1]);
                MMA16816(o[2*np1+1], ph[k2], vh1[2], vh1[3]);
            }
        }
    }

    // epilogue: ctx = O / l -> plain fp16
    const float inv0 = 1.0f / l0v, inv1 = 1.0f / l1v;
    const int b = bh >> 4, h = bh & 15;
    const int gr0 = q0 + w * 16 + (lane >> 2);
    const size_t ro0 = (size_t)(b * SEQ + gr0) * EMB + h * HDIM;
    const size_t ro1 = (size_t)(b * SEQ + gr0 + 8) * EMB + h * HDIM;
#pragma unroll
    for (int nt = 0; nt < 16; nt++) {
        const int col = nt * 8 + (lane & 3) * 2;
        *(uint32_t*)(ctx + ro0 + col) = cvt_plain_h(o[nt][0] * inv0, o[nt][1] * inv0);
        *(uint32_t*)(ctx + ro1 + col) = cvt_plain_h(o[nt][2] * inv1, o[nt][3] * inv1);
    }
}

// ---------------------------------------------------------------------------
extern "C" void kernel_launch(void* const* d_in, const int* in_sizes, int n_in,
                              void* d_out, int out_size)
{
    const float* x      = (const float*)d_in[0];
    const float* wqkv_w = (const float*)d_in[1];
    const float* wqkv_b = (const float*)d_in[2];
    const float* out_w  = (const float*)d_in[3];
    const float* out_b  = (const float*)d_in[4];
    float* out = (float*)d_out;

    float* qkv;
    __half *x16, *w16, *o16w;
    __half *qp, *kh, *kl, *vp, *c16;
    cudaGetSymbolAddress((void**)&qkv, g_qkv);
    cudaGetSymbolAddress((void**)&x16, g_x16);
    cudaGetSymbolAddress((void**)&w16, g_w16);
    cudaGetSymbolAddress((void**)&o16w, g_o16w);
    cudaGetSymbolAddress((void**)&qp, g_qp);
    cudaGetSymbolAddress((void**)&kh, g_khh); cudaGetSymbolAddress((void**)&kl, g_kll);
    cudaGetSymbolAddress((void**)&vp, g_vp);
    cudaGetSymbolAddress((void**)&c16, g_c16);

    cudaFuncSetAttribute(gemm_fp16, cudaFuncAttributeMaxDynamicSharedMemorySize, GEMM_SMEM);
    cudaFuncSetAttribute(flash_mma, cudaFuncAttributeMaxDynamicSharedMemorySize, FLASH_SMEM);

    int n4;
    n4 = MROWS * EMB / 4;
    cvt_f32_h<<<(n4 + 255) / 256, 256>>>((const float4*)x, (uint2*)x16, n4);
    n4 = THREE_E * EMB / 4;
    cvt_f32_h<<<(n4 + 255) / 256, 256>>>((const float4*)wqkv_w, (uint2*)w16, n4);
    n4 = EMB * EMB / 4;
    cvt_f32_h<<<(n4 + 255) / 256, 256>>>((const float4*)out_w, (uint2*)o16w, n4);

    dim3 g1(THREE_E / 128, MROWS / 128);
    gemm_fp16<<<g1, 256, GEMM_SMEM>>>(x16, w16, wqkv_b, qkv, THREE_E, EMB);

    int nr = NBH * SEQ * 64;
    rope_split<<<(nr + 255) / 256, 256>>>(qkv, qp, kh, kl, vp);

    dim3 g2(SEQ / 128, NBH);
    flash_mma<<<g2, 256, FLASH_SMEM>>>(qp, kh, kl, vp, c16);

    dim3 g3(EMB / 128, MROWS / 128);
    gemm_fp16<<<g3, 256, GEMM_SMEM>>>(c16, o16w, out_b, out, EMB, EMB);
}

// round 13
// speedup vs baseline: 1.0589x; 1.0589x over previous
#include <cuda_runtime.h>
#include <cuda_fp16.h>
#include <math.h>
#include <stdint.h>

#define BATCH 2
#define SEQ   2048
#define EMB   2048
#define HEADS 16
#define HDIM  128
#define THREE_E 6144
#define MROWS (BATCH*SEQ)     // 4096
#define NBH   (BATCH*HEADS)   // 32

// ---------------- scratch (__device__ globals; no cudaMalloc) ----------------
__device__ __half g_x16[(size_t)MROWS * EMB];                    // x plain fp16
__device__ __half g_w16[(size_t)THREE_E * EMB];                  // wqkv plain fp16
__device__ __half g_o16w[(size_t)EMB * EMB];                     // out_w plain fp16
__device__ __half g_qp[(size_t)NBH*SEQ*HDIM];                    // Q plain fp16
__device__ __half g_khh[(size_t)NBH*SEQ*HDIM], g_kll[(size_t)NBH*SEQ*HDIM];
__device__ __half g_vp[(size_t)NBH*SEQ*HDIM];                    // V plain fp16
__device__ __half g_c16[(size_t)MROWS * EMB];                    // ctx plain fp16

// ---------------- PTX helpers ----------------
__device__ __forceinline__ uint32_t smem_u32(const void* p) {
    uint32_t a;
    asm("{ .reg .u64 t; cvta.to.shared.u64 t, %1; cvt.u32.u64 %0, t; }"
        : "=r"(a) : "l"(p));
    return a;
}
__device__ __forceinline__ uint32_t cvt_plain_h(float f0, float f1) {
    uint32_t h;
    asm("cvt.rn.f16x2.f32 %0, %1, %2;" : "=r"(h) : "f"(f1), "f"(f0));
    return h;
}
#define LDMX4(r0, r1, r2, r3, addr) \
    asm volatile("ldmatrix.sync.aligned.m8n8.x4.shared.b16 {%0,%1,%2,%3}, [%4];" \
        : "=r"(r0), "=r"(r1), "=r"(r2), "=r"(r3) : "r"(addr))
#define LDMT4(r0, r1, r2, r3, addr) \
    asm volatile("ldmatrix.sync.aligned.m8n8.x4.trans.shared.b16 {%0,%1,%2,%3}, [%4];" \
        : "=r"(r0), "=r"(r1), "=r"(r2), "=r"(r3) : "r"(addr))
#define MMA16816(d, a, b0, b1) \
    asm volatile("mma.sync.aligned.m16n8k16.row.col.f32.f16.f16.f32 " \
        "{%0,%1,%2,%3}, {%4,%5,%6,%7}, {%8,%9}, {%0,%1,%2,%3};" \
        : "+f"((d)[0]), "+f"((d)[1]), "+f"((d)[2]), "+f"((d)[3]) \
        : "r"((a)[0]), "r"((a)[1]), "r"((a)[2]), "r"((a)[3]), "r"(b0), "r"(b1))
#define CP16(dst, src) \
    asm volatile("cp.async.cg.shared.global [%0], [%1], 16;" :: "r"(dst), "l"(src))
#define CPCOMMIT() asm volatile("cp.async.commit_group;" ::: "memory")
#define CPWAIT0()  asm volatile("cp.async.wait_group 0;" ::: "memory")
#define CPWAIT1()  asm volatile("cp.async.wait_group 1;" ::: "memory")

// ---------------------------------------------------------------------------
// Prep: fp32 -> plain fp16
// ---------------------------------------------------------------------------
__global__ void cvt_f32_h(const float4* __restrict__ in,
                          uint2* __restrict__ o16, int n4)
{
    int i = blockIdx.x * blockDim.x + threadIdx.x;
    if (i >= n4) return;
    float4 v = in[i];
    o16[i] = make_uint2(cvt_plain_h(v.x, v.y), cvt_plain_h(v.z, v.w));
}

// ---------------------------------------------------------------------------
// Shared GEMM mainloop config: BM=BN=128, BK=64, 256 thr, 3-stage, 2 CTAs/SM
// ---------------------------------------------------------------------------
#define LDS 72                       // 64 fp16 data + 8 pad per row (144 B)
#define A_SB (128 * LDS * 2)         // 18432 B
#define STAGE_SB (2 * A_SB)          // 36864 B (A + B)
#define GEMM_SMEM (3 * STAGE_SB)     // 110592 B  -> 2 CTAs/SM

__device__ __forceinline__ void gemm_issue(
    const __half* A, const __half* B,
    uint32_t sbase, int m0, int n0, int K, int cc, int tid)
{
    const uint32_t stg = sbase + (uint32_t)(cc % 3) * STAGE_SB;
    const int k0 = cc * 64;
#pragma unroll
    for (int i = 0; i < 4; i++) {
        int c = tid + i * 256;       // 0..1023
        int r = c >> 3, sg = c & 7;
        uint32_t dof = (uint32_t)(r * 144 + sg * 16);
        size_t ao = (size_t)(m0 + r) * K + k0 + sg * 8;
        size_t bo = (size_t)(n0 + r) * K + k0 + sg * 8;
        CP16(stg + dof, (const char*)(A + ao));
        CP16(stg + A_SB + dof, (const char*)(B + bo));
    }
    CPCOMMIT();
}

// Mainloop shared by both GEMMs (accumulates into acc[4][4][4])
__device__ __forceinline__ void gemm_mainloop(
    const __half* A, const __half* B, const uint32_t sbase,
    int m0, int n0, int K, int tid, int lane, int wm, int wn,
    float acc[4][4][4])
{
    const int NCH = K >> 6;
    gemm_issue(A, B, sbase, m0, n0, K, 0, tid);
    gemm_issue(A, B, sbase, m0, n0, K, 1, tid);

    const uint32_t a_row  = (uint32_t)(wm * 64 + (lane & 15));
    const uint32_t a_koff = (uint32_t)((lane >> 4) * 8);
    const uint32_t b_row  = (uint32_t)(wn * 32 + (lane & 7) + ((lane >> 4) << 3));
    const uint32_t b_koff = (uint32_t)(((lane >> 3) & 1) * 8);

    for (int c = 0; c < NCH; c++) {
        CPWAIT1();
        __syncthreads();
        if (c + 2 < NCH) gemm_issue(A, B, sbase, m0, n0, K, c + 2, tid);
        else CPCOMMIT();

        const uint32_t stg = sbase + (uint32_t)(c % 3) * STAGE_SB;
#pragma unroll
        for (int ks = 0; ks < 4; ks++) {
            const uint32_t kofs = (uint32_t)(ks * 16);
            uint32_t a[4][4];
#pragma unroll
            for (int mt = 0; mt < 4; mt++) {
                uint32_t adr = stg + ((a_row + mt * 16) * LDS + kofs + a_koff) * 2;
                LDMX4(a[mt][0], a[mt][1], a[mt][2], a[mt][3], adr);
            }
            uint32_t b[2][4];
#pragma unroll
            for (int p = 0; p < 2; p++) {
                uint32_t adr = sbase + (uint32_t)(c % 3) * STAGE_SB + A_SB
                             + ((b_row + p * 16) * LDS + kofs + b_koff) * 2;
                LDMX4(b[p][0], b[p][1], b[p][2], b[p][3], adr);
            }
#pragma unroll
            for (int mt = 0; mt < 4; mt++)
#pragma unroll
                for (int nt = 0; nt < 4; nt++) {
                    const int p = nt >> 1, hh = (nt & 1) * 2;
                    MMA16816(acc[mt][nt], a[mt], b[p][hh], b[p][hh + 1]);
                }
        }
    }
}

// ---------------------------------------------------------------------------
// Out-projection GEMM: writes fp32 C + bias
// ---------------------------------------------------------------------------
__global__ __launch_bounds__(256, 2) void gemm_fp16(
    const __half* __restrict__ A, const __half* __restrict__ B,
    const float* __restrict__ bias, float* __restrict__ C, int N, int K)
{
    extern __shared__ char dsm[];
    __shared__ float sBias[128];

    const int tid  = threadIdx.x;
    const int lane = tid & 31;
    const int wid  = tid >> 5;
    const int wm   = wid >> 2;
    const int wn   = wid & 3;
    const int m0 = blockIdx.y * 128, n0 = blockIdx.x * 128;
    const uint32_t sbase = smem_u32(dsm);

    if (tid < 128) sBias[tid] = bias[n0 + tid];

    float acc[4][4][4];
#pragma unroll
    for (int mt = 0; mt < 4; mt++)
#pragma unroll
        for (int nt = 0; nt < 4; nt++)
#pragma unroll
            for (int r = 0; r < 4; r++) acc[mt][nt][r] = 0.0f;

    gemm_mainloop(A, B, sbase, m0, n0, K, tid, lane, wm, wn, acc);

    const int erow = wm * 64 + (lane >> 2);
    const int ecol = wn * 32 + (lane & 3) * 2;
#pragma unroll
    for (int mt = 0; mt < 4; mt++) {
#pragma unroll
        for (int nt = 0; nt < 4; nt++) {
            const int cc = ecol + nt * 8;
            const float b0 = sBias[cc], b1 = sBias[cc + 1];
            float* p0 = C + (size_t)(m0 + erow + mt * 16) * N + n0 + cc;
            float* p1 = C + (size_t)(m0 + erow + mt * 16 + 8) * N + n0 + cc;
            float2 v0 = {acc[mt][nt][0] + b0, acc[mt][nt][1] + b1};
            float2 v1 = {acc[mt][nt][2] + b0, acc[mt][nt][3] + b1};
            *(float2*)p0 = v0;
            *(float2*)p1 = v1;
        }
    }
}

// ---------------------------------------------------------------------------
// QKV GEMM with fused RoPE/scale/split epilogue.
// N-tile (128 cols) = one (slot, head): slot = bx/16, head = bx%16.
// Epilogue: stage fp32 tile in smem, apply rope, write fp16 outputs.
// ---------------------------------------------------------------------------
#define CT_STRIDE 132   // fp32 stage-tile row stride

__device__ __forceinline__ void split1h(float x, __half* ph, __half* pl) {
    __half h = __float2half_rn(x);
    *ph = h;
    *pl = __float2half_rn(x - __half2float(h));
}

__global__ __launch_bounds__(256, 2) void gemm_qkv(
    const __half* __restrict__ A, const __half* __restrict__ B,
    const float* __restrict__ bias,
    __half* __restrict__ Qp,
    __half* __restrict__ Kh, __half* __restrict__ Kl,
    __half* __restrict__ Vp, int K)
{
    extern __shared__ char dsm[];
    __shared__ float sBias[128];

    const int tid  = threadIdx.x;
    const int lane = tid & 31;
    const int wid  = tid >> 5;
    const int wm   = wid >> 2;
    const int wn   = wid & 3;
    const int m0 = blockIdx.y * 128, n0 = blockIdx.x * 128;
    const uint32_t sbase = smem_u32(dsm);

    if (tid < 128) sBias[tid] = bias[n0 + tid];

    float acc[4][4][4];
#pragma unroll
    for (int mt = 0; mt < 4; mt++)
#pragma unroll
        for (int nt = 0; nt < 4; nt++)
#pragma unroll
            for (int r = 0; r < 4; r++) acc[mt][nt][r] = 0.0f;

    gemm_mainloop(A, B, sbase, m0, n0, K, tid, lane, wm, wn, acc);

    // ---- stage acc + bias into smem fp32 tile (reuse pipeline smem) ----
    __syncthreads();   // all LDSM reads of final chunk done
    float* ctile = (float*)dsm;
    const int erow = wm * 64 + (lane >> 2);
    const int ecol = wn * 32 + (lane & 3) * 2;
#pragma unroll
    for (int mt = 0; mt < 4; mt++) {
#pragma unroll
        for (int nt = 0; nt < 4; nt++) {
            const int cc = ecol + nt * 8;
            const float b0 = sBias[cc], b1 = sBias[cc + 1];
            ctile[(erow + mt * 16) * CT_STRIDE + cc]     = acc[mt][nt][0] + b0;
            ctile[(erow + mt * 16) * CT_STRIDE + cc + 1] = acc[mt][nt][1] + b1;
            ctile[(erow + mt * 16 + 8) * CT_STRIDE + cc]     = acc[mt][nt][2] + b0;
            ctile[(erow + mt * 16 + 8) * CT_STRIDE + cc + 1] = acc[mt][nt][3] + b1;
        }
    }
    __syncthreads();

    // ---- RoPE / split / store ----
    const int slot = blockIdx.x >> 4;      // 0=Q, 1=K, 2=V
    const int h    = blockIdx.x & 15;
    const float scale = 0.08838834764831845f;

#pragma unroll 4
    for (int i = 0; i < 32; i++) {
        int idx = tid + i * 256;           // 0..8191
        int r = idx >> 6, j = idx & 63;
        int row = m0 + r;
        int b = row >> 11;                 // / SEQ
        int s = row & (SEQ - 1);
        size_t dst = ((size_t)(b * HEADS + h) * SEQ + s) * HDIM + j;
        float v1 = ctile[r * CT_STRIDE + j];
        float v2 = ctile[r * CT_STRIDE + j + 64];
        if (slot == 2) {
            Vp[dst]      = __float2half_rn(v1);
            Vp[dst + 64] = __float2half_rn(v2);
        } else {
            float inv = powf(10000.0f, -(float)j / 64.0f);
            float sn, cs;
            sincosf((float)s * inv, &sn, &cs);
            float r1 = v1 * cs - v2 * sn;
            float r2 = v1 * sn + v2 * cs;
            if (slot == 0) {
                Qp[dst]      = __float2half_rn(r1 * scale);
                Qp[dst + 64] = __float2half_rn(r2 * scale);
            } else {
                split1h(r1, Kh + dst, Kl + dst);
                split1h(r2, Kh + dst + 64, Kl + dst + 64);
            }
        }
    }
}

// ---------------------------------------------------------------------------
// Flash attention (round-11 config): Q plain, K hi/lo scores, V plain, causal.
// 128 threads (4 warps x 16 q-rows), 64x64 KV tiles, D=128, 2 CTAs/SM.
// ---------------------------------------------------------------------------
#define FL_STRIDE_B 272                  // 136 fp16 per smem row
#define FL_TILE (64 * FL_STRIDE_B)       // 17408 B
#define FLASH_SMEM (4 * FL_TILE)         // 69632 B

__global__ __launch_bounds__(128, 2) void flash_mma(
    const __half* __restrict__ Qp,
    const __half* __restrict__ Kh, const __half* __restrict__ Kl,
    const __half* __restrict__ Vp,
    __half* __restrict__ ctx)
{
    extern __shared__ char fsm[];
    const int qt = gridDim.x - 1 - blockIdx.x;   // heavy tiles first
    const int bh = blockIdx.y;
    const int tid = threadIdx.x, lane = tid & 31, w = tid >> 5;
    const int q0 = qt * 64;
    const uint32_t sb = smem_u32(fsm);

    {
        const size_t qo = ((size_t)bh * SEQ + q0) * HDIM;
#pragma unroll
        for (int i = 0; i < 8; i++) {
            int c = tid + i * 128;
            int r = c >> 4, sg = c & 15;
            *(uint4*)(fsm + r * FL_STRIDE_B + sg * 16) =
                *(const uint4*)(Qp + qo + r * HDIM + sg * 8);
        }
    }

    float m0v = -1e30f, m1v = -1e30f, l0v = 0.0f, l1v = 0.0f;
    float o[16][4];
#pragma unroll
    for (int nt = 0; nt < 16; nt++)
#pragma unroll
        for (int r = 0; r < 4; r++) o[nt][r] = 0.0f;

    const uint32_t a_row  = (uint32_t)(w * 16 + (lane & 15));
    const uint32_t a_koff = (uint32_t)((lane >> 4) * 8);
    const uint32_t b_row  = (uint32_t)((lane & 7) + ((lane >> 4) << 3));
    const uint32_t b_koff = (uint32_t)(((lane >> 3) & 1) * 8);
    const uint32_t v_row  = (uint32_t)(lane & 15);
    const uint32_t v_coff = (uint32_t)((lane >> 4) * 8);

    for (int kt = 0; kt <= qt; kt++) {
        __syncthreads();

        const size_t ko = ((size_t)bh * SEQ + kt * 64) * HDIM;
#pragma unroll
        for (int i = 0; i < 8; i++) {
            int c = tid + i * 128;
            int r = c >> 4, sg = c & 15;
            uint32_t dof = (uint32_t)(r * FL_STRIDE_B + sg * 16);
            size_t so = ko + r * HDIM + sg * 8;
            CP16(sb + 1 * FL_TILE + dof, (const char*)(Kh + so));
            CP16(sb + 2 * FL_TILE + dof, (const char*)(Kl + so));
        }
        CPCOMMIT();
#pragma unroll
        for (int i = 0; i < 8; i++) {
            int c = tid + i * 128;
            int r = c >> 4, sg = c & 15;
            uint32_t dof = (uint32_t)(r * FL_STRIDE_B + sg * 16);
            size_t so = ko + r * HDIM + sg * 8;
            CP16(sb + 3 * FL_TILE + dof, (const char*)(Vp + so));
        }
        CPCOMMIT();

        CPWAIT1();
        __syncthreads();

        float s[8][4];
#pragma unroll
        for (int nt = 0; nt < 8; nt++)
#pragma unroll
            for (int r = 0; r < 4; r++) s[nt][r] = 0.0f;

#pragma unroll
        for (int ks = 0; ks < 8; ks++) {
            uint32_t q[4];
            uint32_t qadr = sb + a_row * FL_STRIDE_B + (ks * 16 + a_koff) * 2;
            LDMX4(q[0], q[1], q[2], q[3], qadr);
            uint32_t khf[4][4], klf[4][4];
#pragma unroll
            for (int np = 0; np < 4; np++) {
                uint32_t kadr = sb + 1 * FL_TILE
                              + (np * 16 + b_row) * FL_STRIDE_B
                              + (ks * 16 + b_koff) * 2;
                LDMX4(khf[np][0], khf[np][1], khf[np][2], khf[np][3], kadr);
                LDMX4(klf[np][0], klf[np][1], klf[np][2], klf[np][3], kadr + FL_TILE);
            }
#pragma unroll
            for (int np = 0; np < 4; np++) {
                MMA16816(s[2*np],   q, khf[np][0], khf[np][1]);
                MMA16816(s[2*np+1], q, khf[np][2], khf[np][3]);
            }
#pragma unroll
            for (int np = 0; np < 4; np++) {
                MMA16816(s[2*np],   q, klf[np][0], klf[np][1]);
                MMA16816(s[2*np+1], q, klf[np][2], klf[np][3]);
            }
        }

        if (kt == qt) {
            const int r0 = w * 16 + (lane >> 2);
            const int r1 = r0 + 8;
#pragma unroll
            for (int nt = 0; nt < 8; nt++) {
                const int cb = nt * 8 + (lane & 3) * 2;
                if (cb     > r0) s[nt][0] = -1e30f;
                if (cb + 1 > r0) s[nt][1] = -1e30f;
                if (cb     > r1) s[nt][2] = -1e30f;
                if (cb + 1 > r1) s[nt][3] = -1e30f;
            }
        }

        float mx0 = -1e30f, mx1 = -1e30f;
#pragma unroll
        for (int nt = 0; nt < 8; nt++) {
            mx0 = fmaxf(mx0, fmaxf(s[nt][0], s[nt][1]));
            mx1 = fmaxf(mx1, fmaxf(s[nt][2], s[nt][3]));
        }
        mx0 = fmaxf(mx0, __shfl_xor_sync(0xffffffffu, mx0, 1));
        mx0 = fmaxf(mx0, __shfl_xor_sync(0xffffffffu, mx0, 2));
        mx1 = fmaxf(mx1, __shfl_xor_sync(0xffffffffu, mx1, 1));
        mx1 = fmaxf(mx1, __shfl_xor_sync(0xffffffffu, mx1, 2));

        float mn0 = fmaxf(m0v, mx0), mn1 = fmaxf(m1v, mx1);
        float sf0 = __expf(m0v - mn0), sf1 = __expf(m1v - mn1);
        m0v = mn0; m1v = mn1;

        float ls0 = 0.0f, ls1 = 0.0f;
#pragma unroll
        for (int nt = 0; nt < 8; nt++) {
            s[nt][0] = __expf(s[nt][0] - mn0); ls0 += s[nt][0];
            s[nt][1] = __expf(s[nt][1] - mn0); ls0 += s[nt][1];
            s[nt][2] = __expf(s[nt][2] - mn1); ls1 += s[nt][2];
            s[nt][3] = __expf(s[nt][3] - mn1); ls1 += s[nt][3];
        }
        ls0 += __shfl_xor_sync(0xffffffffu, ls0, 1);
        ls0 += __shfl_xor_sync(0xffffffffu, ls0, 2);
        ls1 += __shfl_xor_sync(0xffffffffu, ls1, 1);
        ls1 += __shfl_xor_sync(0xffffffffu, ls1, 2);
        l0v = l0v * sf0 + ls0;
        l1v = l1v * sf1 + ls1;
#pragma unroll
        for (int nt = 0; nt < 16; nt++) {
            o[nt][0] *= sf0; o[nt][1] *= sf0;
            o[nt][2] *= sf1; o[nt][3] *= sf1;
        }

        uint32_t ph[4][4];
#pragma unroll
        for (int k2 = 0; k2 < 4; k2++) {
            ph[k2][0] = cvt_plain_h(s[2*k2][0],   s[2*k2][1]);
            ph[k2][1] = cvt_plain_h(s[2*k2][2],   s[2*k2][3]);
            ph[k2][2] = cvt_plain_h(s[2*k2+1][0], s[2*k2+1][1]);
            ph[k2][3] = cvt_plain_h(s[2*k2+1][2], s[2*k2+1][3]);
        }

        CPWAIT0();
        __syncthreads();

#pragma unroll
        for (int k2 = 0; k2 < 4; k2++) {
#pragma unroll
            for (int npp = 0; npp < 4; npp++) {
                const int np0 = 2 * npp, np1 = 2 * npp + 1;
                uint32_t vh0[4], vh1[4];
                uint32_t va0 = sb + 3 * FL_TILE
                             + (k2 * 16 + v_row) * FL_STRIDE_B
                             + (np0 * 16 + v_coff) * 2;
                uint32_t va1 = va0 + 32;
                LDMT4(vh0[0], vh0[1], vh0[2], vh0[3], va0);
                LDMT4(vh1[0], vh1[1], vh1[2], vh1[3], va1);
                MMA16816(o[2*np0],   ph[k2], vh0[0], vh0[1]);
                MMA16816(o[2*np0+1], ph[k2], vh0[2], vh0[3]);
                MMA16816(o[2*np1],   ph[k2], vh1[0], vh1[1]);
                MMA16816(o[2*np1+1], ph[k2], vh1[2], vh1[3]);
            }
        }
    }

    const float inv0 = 1.0f / l0v, inv1 = 1.0f / l1v;
    const int b = bh >> 4, h = bh & 15;
    const int gr0 = q0 + w * 16 + (lane >> 2);
    const size_t ro0 = (size_t)(b * SEQ + gr0) * EMB + h * HDIM;
    const size_t ro1 = (size_t)(b * SEQ + gr0 + 8) * EMB + h * HDIM;
#pragma unroll
    for (int nt = 0; nt < 16; nt++) {
        const int col = nt * 8 + (lane & 3) * 2;
        *(uint32_t*)(ctx + ro0 + col) = cvt_plain_h(o[nt][0] * inv0, o[nt][1] * inv0);
        *(uint32_t*)(ctx + ro1 + col) = cvt_plain_h(o[nt][2] * inv1, o[nt][3] * inv1);
    }
}

// ---------------------------------------------------------------------------
extern "C" void kernel_launch(void* const* d_in, const int* in_sizes, int n_in,
                              void* d_out, int out_size)
{
    const float* x      = (const float*)d_in[0];
    const float* wqkv_w = (const float*)d_in[1];
    const float* wqkv_b = (const float*)d_in[2];
    const float* out_w  = (const float*)d_in[3];
    const float* out_b  = (const float*)d_in[4];
    float* out = (float*)d_out;

    __half *x16, *w16, *o16w;
    __half *qp, *kh, *kl, *vp, *c16;
    cudaGetSymbolAddress((void**)&x16, g_x16);
    cudaGetSymbolAddress((void**)&w16, g_w16);
    cudaGetSymbolAddress((void**)&o16w, g_o16w);
    cudaGetSymbolAddress((void**)&qp, g_qp);
    cudaGetSymbolAddress((void**)&kh, g_khh); cudaGetSymbolAddress((void**)&kl, g_kll);
    cudaGetSymbolAddress((void**)&vp, g_vp);
    cudaGetSymbolAddress((void**)&c16, g_c16);

    cudaFuncSetAttribute(gemm_fp16, cudaFuncAttributeMaxDynamicSharedMemorySize, GEMM_SMEM);
    cudaFuncSetAttribute(gemm_qkv, cudaFuncAttributeMaxDynamicSharedMemorySize, GEMM_SMEM);
    cudaFuncSetAttribute(flash_mma, cudaFuncAttributeMaxDynamicSharedMemorySize, FLASH_SMEM);

    int n4;
    n4 = MROWS * EMB / 4;
    cvt_f32_h<<<(n4 + 255) / 256, 256>>>((const float4*)x, (uint2*)x16, n4);
    n4 = THREE_E * EMB / 4;
    cvt_f32_h<<<(n4 + 255) / 256, 256>>>((const float4*)wqkv_w, (uint2*)w16, n4);
    n4 = EMB * EMB / 4;
    cvt_f32_h<<<(n4 + 255) / 256, 256>>>((const float4*)out_w, (uint2*)o16w, n4);

    // QKV projection with fused RoPE/split epilogue
    dim3 g1(THREE_E / 128, MROWS / 128);
    gemm_qkv<<<g1, 256, GEMM_SMEM>>>(x16, w16, wqkv_b, qp, kh, kl, vp, EMB);

    // attention (round-11 geometry: 64-row Q blocks, 1024 CTAs -> good balance)
    dim3 g2(SEQ / 64, NBH);
    flash_mma<<<g2, 128, FLASH_SMEM>>>(qp, kh, kl, vp, c16);

    // output projection
    dim3 g3(EMB / 128, MROWS / 128);
    gemm_fp16<<<g3, 256, GEMM_SMEM>>>(c16, o16w, out_b, out, EMB, EMB);
}

// round 14
// speedup vs baseline: 1.0727x; 1.0130x over previous
#include <cuda_runtime.h>
#include <cuda_fp16.h>
#include <math.h>
#include <stdint.h>

#define BATCH 2
#define SEQ   2048
#define EMB   2048
#define HEADS 16
#define HDIM  128
#define THREE_E 6144
#define MROWS (BATCH*SEQ)     // 4096
#define NBH   (BATCH*HEADS)   // 32

// ---------------- scratch (__device__ globals; no cudaMalloc) ----------------
__device__ __half g_x16[(size_t)MROWS * EMB];                    // x plain fp16
__device__ __half g_w16[(size_t)THREE_E * EMB];                  // wqkv plain fp16
__device__ __half g_o16w[(size_t)EMB * EMB];                     // out_w plain fp16
__device__ __half g_qp[(size_t)NBH*SEQ*HDIM];                    // Q plain fp16
__device__ __half g_khh[(size_t)NBH*SEQ*HDIM], g_kll[(size_t)NBH*SEQ*HDIM];
__device__ __half g_vp[(size_t)NBH*SEQ*HDIM];                    // V plain fp16
__device__ __half g_c16[(size_t)MROWS * EMB];                    // ctx plain fp16
__device__ float  g_rope[(size_t)SEQ * 64 * 2];                  // (cos,sin) table

// ---------------- PTX helpers ----------------
__device__ __forceinline__ uint32_t smem_u32(const void* p) {
    uint32_t a;
    asm("{ .reg .u64 t; cvta.to.shared.u64 t, %1; cvt.u32.u64 %0, t; }"
        : "=r"(a) : "l"(p));
    return a;
}
__device__ __forceinline__ uint32_t cvt_plain_h(float f0, float f1) {
    uint32_t h;
    asm("cvt.rn.f16x2.f32 %0, %1, %2;" : "=r"(h) : "f"(f1), "f"(f0));
    return h;
}
#define LDMX4(r0, r1, r2, r3, addr) \
    asm volatile("ldmatrix.sync.aligned.m8n8.x4.shared.b16 {%0,%1,%2,%3}, [%4];" \
        : "=r"(r0), "=r"(r1), "=r"(r2), "=r"(r3) : "r"(addr))
#define LDMT4(r0, r1, r2, r3, addr) \
    asm volatile("ldmatrix.sync.aligned.m8n8.x4.trans.shared.b16 {%0,%1,%2,%3}, [%4];" \
        : "=r"(r0), "=r"(r1), "=r"(r2), "=r"(r3) : "r"(addr))
#define MMA16816(d, a, b0, b1) \
    asm volatile("mma.sync.aligned.m16n8k16.row.col.f32.f16.f16.f32 " \
        "{%0,%1,%2,%3}, {%4,%5,%6,%7}, {%8,%9}, {%0,%1,%2,%3};" \
        : "+f"((d)[0]), "+f"((d)[1]), "+f"((d)[2]), "+f"((d)[3]) \
        : "r"((a)[0]), "r"((a)[1]), "r"((a)[2]), "r"((a)[3]), "r"(b0), "r"(b1))
#define CP16(dst, src) \
    asm volatile("cp.async.cg.shared.global [%0], [%1], 16;" :: "r"(dst), "l"(src))
#define CPCOMMIT() asm volatile("cp.async.commit_group;" ::: "memory")
#define CPWAIT0()  asm volatile("cp.async.wait_group 0;" ::: "memory")
#define CPWAIT1()  asm volatile("cp.async.wait_group 1;" ::: "memory")

// ---------------------------------------------------------------------------
// Prep: fp32 -> plain fp16 ; RoPE table
// ---------------------------------------------------------------------------
__global__ void cvt_f32_h(const float4* __restrict__ in,
                          uint2* __restrict__ o16, int n4)
{
    int i = blockIdx.x * blockDim.x + threadIdx.x;
    if (i >= n4) return;
    float4 v = in[i];
    o16[i] = make_uint2(cvt_plain_h(v.x, v.y), cvt_plain_h(v.z, v.w));
}

__global__ void rope_table(float* __restrict__ tab)
{
    int idx = blockIdx.x * blockDim.x + threadIdx.x;   // SEQ*64
    if (idx >= SEQ * 64) return;
    int j = idx & 63, s = idx >> 6;
    float inv = powf(10000.0f, -(float)j / 64.0f);
    float sn, cs;
    sincosf((float)s * inv, &sn, &cs);
    tab[idx * 2]     = cs;
    tab[idx * 2 + 1] = sn;
}

// ---------------------------------------------------------------------------
// Shared GEMM mainloop config: BM=BN=128, BK=64, 256 thr, 3-stage, 2 CTAs/SM
// ---------------------------------------------------------------------------
#define LDS 72                       // 64 fp16 data + 8 pad per row (144 B)
#define A_SB (128 * LDS * 2)         // 18432 B
#define STAGE_SB (2 * A_SB)          // 36864 B (A + B)
#define GEMM_SMEM (3 * STAGE_SB)     // 110592 B  -> 2 CTAs/SM

__device__ __forceinline__ void gemm_issue(
    const __half* A, const __half* B,
    uint32_t sbase, int m0, int n0, int K, int cc, int tid)
{
    const uint32_t stg = sbase + (uint32_t)(cc % 3) * STAGE_SB;
    const int k0 = cc * 64;
#pragma unroll
    for (int i = 0; i < 4; i++) {
        int c = tid + i * 256;       // 0..1023
        int r = c >> 3, sg = c & 7;
        uint32_t dof = (uint32_t)(r * 144 + sg * 16);
        size_t ao = (size_t)(m0 + r) * K + k0 + sg * 8;
        size_t bo = (size_t)(n0 + r) * K + k0 + sg * 8;
        CP16(stg + dof, (const char*)(A + ao));
        CP16(stg + A_SB + dof, (const char*)(B + bo));
    }
    CPCOMMIT();
}

__device__ __forceinline__ void gemm_mainloop(
    const __half* A, const __half* B, const uint32_t sbase,
    int m0, int n0, int K, int tid, int lane, int wm, int wn,
    float acc[4][4][4])
{
    const int NCH = K >> 6;
    gemm_issue(A, B, sbase, m0, n0, K, 0, tid);
    gemm_issue(A, B, sbase, m0, n0, K, 1, tid);

    const uint32_t a_row  = (uint32_t)(wm * 64 + (lane & 15));
    const uint32_t a_koff = (uint32_t)((lane >> 4) * 8);
    const uint32_t b_row  = (uint32_t)(wn * 32 + (lane & 7) + ((lane >> 4) << 3));
    const uint32_t b_koff = (uint32_t)(((lane >> 3) & 1) * 8);

    for (int c = 0; c < NCH; c++) {
        CPWAIT1();
        __syncthreads();
        if (c + 2 < NCH) gemm_issue(A, B, sbase, m0, n0, K, c + 2, tid);
        else CPCOMMIT();

        const uint32_t stg = sbase + (uint32_t)(c % 3) * STAGE_SB;
#pragma unroll
        for (int ks = 0; ks < 4; ks++) {
            const uint32_t kofs = (uint32_t)(ks * 16);
            uint32_t a[4][4];
#pragma unroll
            for (int mt = 0; mt < 4; mt++) {
                uint32_t adr = stg + ((a_row + mt * 16) * LDS + kofs + a_koff) * 2;
                LDMX4(a[mt][0], a[mt][1], a[mt][2], a[mt][3], adr);
            }
            uint32_t b[2][4];
#pragma unroll
            for (int p = 0; p < 2; p++) {
                uint32_t adr = stg + A_SB
                             + ((b_row + p * 16) * LDS + kofs + b_koff) * 2;
                LDMX4(b[p][0], b[p][1], b[p][2], b[p][3], adr);
            }
#pragma unroll
            for (int mt = 0; mt < 4; mt++)
#pragma unroll
                for (int nt = 0; nt < 4; nt++) {
                    const int p = nt >> 1, hh = (nt & 1) * 2;
                    MMA16816(acc[mt][nt], a[mt], b[p][hh], b[p][hh + 1]);
                }
        }
    }
}

// ---------------------------------------------------------------------------
// Out-projection GEMM: writes fp32 C + bias
// ---------------------------------------------------------------------------
__global__ __launch_bounds__(256, 2) void gemm_fp16(
    const __half* __restrict__ A, const __half* __restrict__ B,
    const float* __restrict__ bias, float* __restrict__ C, int N, int K)
{
    extern __shared__ char dsm[];
    __shared__ float sBias[128];

    const int tid  = threadIdx.x;
    const int lane = tid & 31;
    const int wid  = tid >> 5;
    const int wm   = wid >> 2;
    const int wn   = wid & 3;
    const int m0 = blockIdx.y * 128, n0 = blockIdx.x * 128;
    const uint32_t sbase = smem_u32(dsm);

    if (tid < 128) sBias[tid] = bias[n0 + tid];

    float acc[4][4][4];
#pragma unroll
    for (int mt = 0; mt < 4; mt++)
#pragma unroll
        for (int nt = 0; nt < 4; nt++)
#pragma unroll
            for (int r = 0; r < 4; r++) acc[mt][nt][r] = 0.0f;

    gemm_mainloop(A, B, sbase, m0, n0, K, tid, lane, wm, wn, acc);

    const int erow = wm * 64 + (lane >> 2);
    const int ecol = wn * 32 + (lane & 3) * 2;
#pragma unroll
    for (int mt = 0; mt < 4; mt++) {
#pragma unroll
        for (int nt = 0; nt < 4; nt++) {
            const int cc = ecol + nt * 8;
            const float b0 = sBias[cc], b1 = sBias[cc + 1];
            float* p0 = C + (size_t)(m0 + erow + mt * 16) * N + n0 + cc;
            float* p1 = C + (size_t)(m0 + erow + mt * 16 + 8) * N + n0 + cc;
            float2 v0 = {acc[mt][nt][0] + b0, acc[mt][nt][1] + b1};
            float2 v1 = {acc[mt][nt][2] + b0, acc[mt][nt][3] + b1};
            *(float2*)p0 = v0;
            *(float2*)p1 = v1;
        }
    }
}

// ---------------------------------------------------------------------------
// QKV GEMM with fused RoPE/scale/split epilogue (table-driven trig).
// N-tile (128 cols) = one (slot, head): slot = bx/16, head = bx%16.
// ---------------------------------------------------------------------------
#define CT_STRIDE 132   // fp32 stage-tile row stride

__device__ __forceinline__ void split1h(float x, __half* ph, __half* pl) {
    __half h = __float2half_rn(x);
    *ph = h;
    *pl = __float2half_rn(x - __half2float(h));
}

__global__ __launch_bounds__(256, 2) void gemm_qkv(
    const __half* __restrict__ A, const __half* __restrict__ B,
    const float* __restrict__ bias, const float* __restrict__ rope,
    __half* __restrict__ Qp,
    __half* __restrict__ Kh, __half* __restrict__ Kl,
    __half* __restrict__ Vp, int K)
{
    extern __shared__ char dsm[];
    __shared__ float sBias[128];

    const int tid  = threadIdx.x;
    const int lane = tid & 31;
    const int wid  = tid >> 5;
    const int wm   = wid >> 2;
    const int wn   = wid & 3;
    const int m0 = blockIdx.y * 128, n0 = blockIdx.x * 128;
    const uint32_t sbase = smem_u32(dsm);

    if (tid < 128) sBias[tid] = bias[n0 + tid];

    float acc[4][4][4];
#pragma unroll
    for (int mt = 0; mt < 4; mt++)
#pragma unroll
        for (int nt = 0; nt < 4; nt++)
#pragma unroll
            for (int r = 0; r < 4; r++) acc[mt][nt][r] = 0.0f;

    gemm_mainloop(A, B, sbase, m0, n0, K, tid, lane, wm, wn, acc);

    // ---- stage acc + bias into smem fp32 tile (reuse pipeline smem) ----
    __syncthreads();
    float* ctile = (float*)dsm;
    const int erow = wm * 64 + (lane >> 2);
    const int ecol = wn * 32 + (lane & 3) * 2;
#pragma unroll
    for (int mt = 0; mt < 4; mt++) {
#pragma unroll
        for (int nt = 0; nt < 4; nt++) {
            const int cc = ecol + nt * 8;
            const float b0 = sBias[cc], b1 = sBias[cc + 1];
            ctile[(erow + mt * 16) * CT_STRIDE + cc]     = acc[mt][nt][0] + b0;
            ctile[(erow + mt * 16) * CT_STRIDE + cc + 1] = acc[mt][nt][1] + b1;
            ctile[(erow + mt * 16 + 8) * CT_STRIDE + cc]     = acc[mt][nt][2] + b0;
            ctile[(erow + mt * 16 + 8) * CT_STRIDE + cc + 1] = acc[mt][nt][3] + b1;
        }
    }
    __syncthreads();

    // ---- RoPE / split / store (trig from table) ----
    const int slot = blockIdx.x >> 4;      // 0=Q, 1=K, 2=V
    const int h    = blockIdx.x & 15;
    const float scale = 0.08838834764831845f;

#pragma unroll 4
    for (int i = 0; i < 32; i++) {
        int idx = tid + i * 256;           // 0..8191
        int r = idx >> 6, j = idx & 63;
        int row = m0 + r;
        int b = row >> 11;                 // / SEQ
        int s = row & (SEQ - 1);
        size_t dst = ((size_t)(b * HEADS + h) * SEQ + s) * HDIM + j;
        float v1 = ctile[r * CT_STRIDE + j];
        float v2 = ctile[r * CT_STRIDE + j + 64];
        if (slot == 2) {
            Vp[dst]      = __float2half_rn(v1);
            Vp[dst + 64] = __float2half_rn(v2);
        } else {
            float2 cssn = *(const float2*)(rope + (size_t)(s * 64 + j) * 2);
            float r1 = v1 * cssn.x - v2 * cssn.y;
            float r2 = v1 * cssn.y + v2 * cssn.x;
            if (slot == 0) {
                Qp[dst]      = __float2half_rn(r1 * scale);
                Qp[dst + 64] = __float2half_rn(r2 * scale);
            } else {
                split1h(r1, Kh + dst, Kl + dst);
                split1h(r2, Kh + dst + 64, Kl + dst + 64);
            }
        }
    }
}

// ---------------------------------------------------------------------------
// Flash attention: Q plain, K hi/lo scores, V plain, causal.
// 128 threads (4 warps x 16 q-rows), 64x64 KV tiles, D=128, 3 CTAs/SM.
// ---------------------------------------------------------------------------
#define FL_STRIDE_B 272                  // 136 fp16 per smem row
#define FL_TILE (64 * FL_STRIDE_B)       // 17408 B
#define FLASH_SMEM (4 * FL_TILE)         // 69632 B -> 3 CTAs/SM

__global__ __launch_bounds__(128, 3) void flash_mma(
    const __half* __restrict__ Qp,
    const __half* __restrict__ Kh, const __half* __restrict__ Kl,
    const __half* __restrict__ Vp,
    __half* __restrict__ ctx)
{
    extern __shared__ char fsm[];
    const int qt = gridDim.x - 1 - blockIdx.x;   // heavy tiles first
    const int bh = blockIdx.y;
    const int tid = threadIdx.x, lane = tid & 31, w = tid >> 5;
    const int q0 = qt * 64;
    const uint32_t sb = smem_u32(fsm);

    {
        const size_t qo = ((size_t)bh * SEQ + q0) * HDIM;
#pragma unroll
        for (int i = 0; i < 8; i++) {
            int c = tid + i * 128;
            int r = c >> 4, sg = c & 15;
            *(uint4*)(fsm + r * FL_STRIDE_B + sg * 16) =
                *(const uint4*)(Qp + qo + r * HDIM + sg * 8);
        }
    }

    float m0v = -1e30f, m1v = -1e30f, l0v = 0.0f, l1v = 0.0f;
    float o[16][4];
#pragma unroll
    for (int nt = 0; nt < 16; nt++)
#pragma unroll
        for (int r = 0; r < 4; r++) o[nt][r] = 0.0f;

    const uint32_t a_row  = (uint32_t)(w * 16 + (lane & 15));
    const uint32_t a_koff = (uint32_t)((lane >> 4) * 8);
    const uint32_t b_row  = (uint32_t)((lane & 7) + ((lane >> 4) << 3));
    const uint32_t b_koff = (uint32_t)(((lane >> 3) & 1) * 8);
    const uint32_t v_row  = (uint32_t)(lane & 15);
    const uint32_t v_coff = (uint32_t)((lane >> 4) * 8);

    for (int kt = 0; kt <= qt; kt++) {
        __syncthreads();

        const size_t ko = ((size_t)bh * SEQ + kt * 64) * HDIM;
#pragma unroll
        for (int i = 0; i < 8; i++) {
            int c = tid + i * 128;
            int r = c >> 4, sg = c & 15;
            uint32_t dof = (uint32_t)(r * FL_STRIDE_B + sg * 16);
            size_t so = ko + r * HDIM + sg * 8;
            CP16(sb + 1 * FL_TILE + dof, (const char*)(Kh + so));
            CP16(sb + 2 * FL_TILE + dof, (const char*)(Kl + so));
        }
        CPCOMMIT();
#pragma unroll
        for (int i = 0; i < 8; i++) {
            int c = tid + i * 128;
            int r = c >> 4, sg = c & 15;
            uint32_t dof = (uint32_t)(r * FL_STRIDE_B + sg * 16);
            size_t so = ko + r * HDIM + sg * 8;
            CP16(sb + 3 * FL_TILE + dof, (const char*)(Vp + so));
        }
        CPCOMMIT();

        CPWAIT1();
        __syncthreads();

        float s[8][4];
#pragma unroll
        for (int nt = 0; nt < 8; nt++)
#pragma unroll
            for (int r = 0; r < 4; r++) s[nt][r] = 0.0f;

#pragma unroll
        for (int ks = 0; ks < 8; ks++) {
            uint32_t q[4];
            uint32_t qadr = sb + a_row * FL_STRIDE_B + (ks * 16 + a_koff) * 2;
            LDMX4(q[0], q[1], q[2], q[3], qadr);
            uint32_t khf[4][4], klf[4][4];
#pragma unroll
            for (int np = 0; np < 4; np++) {
                uint32_t kadr = sb + 1 * FL_TILE
                              + (np * 16 + b_row) * FL_STRIDE_B
                              + (ks * 16 + b_koff) * 2;
                LDMX4(khf[np][0], khf[np][1], khf[np][2], khf[np][3], kadr);
                LDMX4(klf[np][0], klf[np][1], klf[np][2], klf[np][3], kadr + FL_TILE);
            }
#pragma unroll
            for (int np = 0; np < 4; np++) {
                MMA16816(s[2*np],   q, khf[np][0], khf[np][1]);
                MMA16816(s[2*np+1], q, khf[np][2], khf[np][3]);
            }
#pragma unroll
            for (int np = 0; np < 4; np++) {
                MMA16816(s[2*np],   q, klf[np][0], klf[np][1]);
                MMA16816(s[2*np+1], q, klf[np][2], klf[np][3]);
            }
        }

        if (kt == qt) {
            const int r0 = w * 16 + (lane >> 2);
            const int r1 = r0 + 8;
#pragma unroll
            for (int nt = 0; nt < 8; nt++) {
                const int cb = nt * 8 + (lane & 3) * 2;
                if (cb     > r0) s[nt][0] = -1e30f;
                if (cb + 1 > r0) s[nt][1] = -1e30f;
                if (cb     > r1) s[nt][2] = -1e30f;
                if (cb + 1 > r1) s[nt][3] = -1e30f;
            }
        }

        float mx0 = -1e30f, mx1 = -1e30f;
#pragma unroll
        for (int nt = 0; nt < 8; nt++) {
            mx0 = fmaxf(mx0, fmaxf(s[nt][0], s[nt][1]));
            mx1 = fmaxf(mx1, fmaxf(s[nt][2], s[nt][3]));
        }
        mx0 = fmaxf(mx0, __shfl_xor_sync(0xffffffffu, mx0, 1));
        mx0 = fmaxf(mx0, __shfl_xor_sync(0xffffffffu, mx0, 2));
        mx1 = fmaxf(mx1, __shfl_xor_sync(0xffffffffu, mx1, 1));
        mx1 = fmaxf(mx1, __shfl_xor_sync(0xffffffffu, mx1, 2));

        float mn0 = fmaxf(m0v, mx0), mn1 = fmaxf(m1v, mx1);
        float sf0 = __expf(m0v - mn0), sf1 = __expf(m1v - mn1);
        m0v = mn0; m1v = mn1;

        float ls0 = 0.0f, ls1 = 0.0f;
#pragma unroll
        for (int nt = 0; nt < 8; nt++) {
            s[nt][0] = __expf(s[nt][0] - mn0); ls0 += s[nt][0];
            s[nt][1] = __expf(s[nt][1] - mn0); ls0 += s[nt][1];
            s[nt][2] = __expf(s[nt][2] - mn1); ls1 += s[nt][2];
            s[nt][3] = __expf(s[nt][3] - mn1); ls1 += s[nt][3];
        }
        ls0 += __shfl_xor_sync(0xffffffffu, ls0, 1);
        ls0 += __shfl_xor_sync(0xffffffffu, ls0, 2);
        ls1 += __shfl_xor_sync(0xffffffffu, ls1, 1);
        ls1 += __shfl_xor_sync(0xffffffffu, ls1, 2);
        l0v = l0v * sf0 + ls0;
        l1v = l1v * sf1 + ls1;
#pragma unroll
        for (int nt = 0; nt < 16; nt++) {
            o[nt][0] *= sf0; o[nt][1] *= sf0;
            o[nt][2] *= sf1; o[nt][3] *= sf1;
        }

        uint32_t ph[4][4];
#pragma unroll
        for (int k2 = 0; k2 < 4; k2++) {
            ph[k2][0] = cvt_plain_h(s[2*k2][0],   s[2*k2][1]);
            ph[k2][1] = cvt_plain_h(s[2*k2][2],   s[2*k2][3]);
            ph[k2][2] = cvt_plain_h(s[2*k2+1][0], s[2*k2+1][1]);
            ph[k2][3] = cvt_plain_h(s[2*k2+1][2], s[2*k2+1][3]);
        }

        CPWAIT0();
        __syncthreads();

#pragma unroll
        for (int k2 = 0; k2 < 4; k2++) {
#pragma unroll
            for (int npp = 0; npp < 4; npp++) {
                const int np0 = 2 * npp, np1 = 2 * npp + 1;
                uint32_t vh0[4], vh1[4];
                uint32_t va0 = sb + 3 * FL_TILE
                             + (k2 * 16 + v_row) * FL_STRIDE_B
                             + (np0 * 16 + v_coff) * 2;
                uint32_t va1 = va0 + 32;
                LDMT4(vh0[0], vh0[1], vh0[2], vh0[3], va0);
                LDMT4(vh1[0], vh1[1], vh1[2], vh1[3], va1);
                MMA16816(o[2*np0],   ph[k2], vh0[0], vh0[1]);
                MMA16816(o[2*np0+1], ph[k2], vh0[2], vh0[3]);
                MMA16816(o[2*np1],   ph[k2], vh1[0], vh1[1]);
                MMA16816(o[2*np1+1], ph[k2], vh1[2], vh1[3]);
            }
        }
    }

    const float inv0 = 1.0f / l0v, inv1 = 1.0f / l1v;
    const int b = bh >> 4, h = bh & 15;
    const int gr0 = q0 + w * 16 + (lane >> 2);
    const size_t ro0 = (size_t)(b * SEQ + gr0) * EMB + h * HDIM;
    const size_t ro1 = (size_t)(b * SEQ + gr0 + 8) * EMB + h * HDIM;
#pragma unroll
    for (int nt = 0; nt < 16; nt++) {
        const int col = nt * 8 + (lane & 3) * 2;
        *(uint32_t*)(ctx + ro0 + col) = cvt_plain_h(o[nt][0] * inv0, o[nt][1] * inv0);
        *(uint32_t*)(ctx + ro1 + col) = cvt_plain_h(o[nt][2] * inv1, o[nt][3] * inv1);
    }
}

// ---------------------------------------------------------------------------
extern "C" void kernel_launch(void* const* d_in, const int* in_sizes, int n_in,
                              void* d_out, int out_size)
{
    const float* x      = (const float*)d_in[0];
    const float* wqkv_w = (const float*)d_in[1];
    const float* wqkv_b = (const float*)d_in[2];
    const float* out_w  = (const float*)d_in[3];
    const float* out_b  = (const float*)d_in[4];
    float* out = (float*)d_out;

    __half *x16, *w16, *o16w;
    __half *qp, *kh, *kl, *vp, *c16;
    float* rope;
    cudaGetSymbolAddress((void**)&x16, g_x16);
    cudaGetSymbolAddress((void**)&w16, g_w16);
    cudaGetSymbolAddress((void**)&o16w, g_o16w);
    cudaGetSymbolAddress((void**)&qp, g_qp);
    cudaGetSymbolAddress((void**)&kh, g_khh); cudaGetSymbolAddress((void**)&kl, g_kll);
    cudaGetSymbolAddress((void**)&vp, g_vp);
    cudaGetSymbolAddress((void**)&c16, g_c16);
    cudaGetSymbolAddress((void**)&rope, g_rope);

    cudaFuncSetAttribute(gemm_fp16, cudaFuncAttributeMaxDynamicSharedMemorySize, GEMM_SMEM);
    cudaFuncSetAttribute(gemm_qkv, cudaFuncAttributeMaxDynamicSharedMemorySize, GEMM_SMEM);
    cudaFuncSetAttribute(flash_mma, cudaFuncAttributeMaxDynamicSharedMemorySize, FLASH_SMEM);

    int n4;
    n4 = MROWS * EMB / 4;
    cvt_f32_h<<<(n4 + 255) / 256, 256>>>((const float4*)x, (uint2*)x16, n4);
    n4 = THREE_E * EMB / 4;
    cvt_f32_h<<<(n4 + 255) / 256, 256>>>((const float4*)wqkv_w, (uint2*)w16, n4);
    n4 = EMB * EMB / 4;
    cvt_f32_h<<<(n4 + 255) / 256, 256>>>((const float4*)out_w, (uint2*)o16w, n4);
    rope_table<<<(SEQ * 64 + 255) / 256, 256>>>(rope);

    // QKV projection with fused RoPE/split epilogue
    dim3 g1(THREE_E / 128, MROWS / 128);
    gemm_qkv<<<g1, 256, GEMM_SMEM>>>(x16, w16, wqkv_b, rope, qp, kh, kl, vp, EMB);

    // attention
    dim3 g2(SEQ / 64, NBH);
    flash_mma<<<g2, 128, FLASH_SMEM>>>(qp, kh, kl, vp, c16);

    // output projection
    dim3 g3(EMB / 128, MROWS / 128);
    gemm_fp16<<<g3, 256, GEMM_SMEM>>>(c16, o16w, out_b, out, EMB, EMB);
}

// round 15
// speedup vs baseline: 1.1666x; 1.0876x over previous
#include <cuda_runtime.h>
#include <cuda_fp16.h>
#include <math.h>
#include <stdint.h>

#define BATCH 2
#define SEQ   2048
#define EMB   2048
#define HEADS 16
#define HDIM  128
#define THREE_E 6144
#define MROWS (BATCH*SEQ)     // 4096
#define NBH   (BATCH*HEADS)   // 32

// ---------------- scratch (__device__ globals; no cudaMalloc) ----------------
__device__ __half g_x16[(size_t)MROWS * EMB];                    // x plain fp16
__device__ __half g_w16[(size_t)THREE_E * EMB];                  // wqkv plain fp16
__device__ __half g_o16w[(size_t)EMB * EMB];                     // out_w plain fp16
__device__ __half g_qp[(size_t)NBH*SEQ*HDIM];                    // Q plain fp16
__device__ __half g_kp[(size_t)NBH*SEQ*HDIM];                    // K plain fp16
__device__ __half g_vp[(size_t)NBH*SEQ*HDIM];                    // V plain fp16
__device__ __half g_c16[(size_t)MROWS * EMB];                    // ctx plain fp16
__device__ float  g_rope[(size_t)SEQ * 64 * 2];                  // (cos,sin) table

// ---------------- PTX helpers ----------------
__device__ __forceinline__ uint32_t smem_u32(const void* p) {
    uint32_t a;
    asm("{ .reg .u64 t; cvta.to.shared.u64 t, %1; cvt.u32.u64 %0, t; }"
        : "=r"(a) : "l"(p));
    return a;
}
__device__ __forceinline__ uint32_t cvt_plain_h(float f0, float f1) {
    uint32_t h;
    asm("cvt.rn.f16x2.f32 %0, %1, %2;" : "=r"(h) : "f"(f1), "f"(f0));
    return h;
}
#define LDMX4(r0, r1, r2, r3, addr) \
    asm volatile("ldmatrix.sync.aligned.m8n8.x4.shared.b16 {%0,%1,%2,%3}, [%4];" \
        : "=r"(r0), "=r"(r1), "=r"(r2), "=r"(r3) : "r"(addr))
#define LDMT4(r0, r1, r2, r3, addr) \
    asm volatile("ldmatrix.sync.aligned.m8n8.x4.trans.shared.b16 {%0,%1,%2,%3}, [%4];" \
        : "=r"(r0), "=r"(r1), "=r"(r2), "=r"(r3) : "r"(addr))
#define MMA16816(d, a, b0, b1) \
    asm volatile("mma.sync.aligned.m16n8k16.row.col.f32.f16.f16.f32 " \
        "{%0,%1,%2,%3}, {%4,%5,%6,%7}, {%8,%9}, {%0,%1,%2,%3};" \
        : "+f"((d)[0]), "+f"((d)[1]), "+f"((d)[2]), "+f"((d)[3]) \
        : "r"((a)[0]), "r"((a)[1]), "r"((a)[2]), "r"((a)[3]), "r"(b0), "r"(b1))
#define CP16(dst, src) \
    asm volatile("cp.async.cg.shared.global [%0], [%1], 16;" :: "r"(dst), "l"(src))
#define CPCOMMIT() asm volatile("cp.async.commit_group;" ::: "memory")
#define CPWAIT0()  asm volatile("cp.async.wait_group 0;" ::: "memory")
#define CPWAIT1()  asm volatile("cp.async.wait_group 1;" ::: "memory")

// ---------------------------------------------------------------------------
// Prep: fp32 -> plain fp16 ; RoPE table
// ---------------------------------------------------------------------------
__global__ void cvt_f32_h(const float4* __restrict__ in,
                          uint2* __restrict__ o16, int n4)
{
    int i = blockIdx.x * blockDim.x + threadIdx.x;
    if (i >= n4) return;
    float4 v = in[i];
    o16[i] = make_uint2(cvt_plain_h(v.x, v.y), cvt_plain_h(v.z, v.w));
}

__global__ void rope_table(float* __restrict__ tab)
{
    int idx = blockIdx.x * blockDim.x + threadIdx.x;   // SEQ*64
    if (idx >= SEQ * 64) return;
    int j = idx & 63, s = idx >> 6;
    float inv = powf(10000.0f, -(float)j / 64.0f);
    float sn, cs;
    sincosf((float)s * inv, &sn, &cs);
    tab[idx * 2]     = cs;
    tab[idx * 2 + 1] = sn;
}

// ---------------------------------------------------------------------------
// Shared GEMM mainloop config: BM=BN=128, BK=64, 256 thr, 3-stage, 2 CTAs/SM
// ---------------------------------------------------------------------------
#define LDS 72                       // 64 fp16 data + 8 pad per row (144 B)
#define A_SB (128 * LDS * 2)         // 18432 B
#define STAGE_SB (2 * A_SB)          // 36864 B (A + B)
#define GEMM_SMEM (3 * STAGE_SB)     // 110592 B  -> 2 CTAs/SM

__device__ __forceinline__ void gemm_issue(
    const __half* A, const __half* B,
    uint32_t sbase, int m0, int n0, int K, int cc, int tid)
{
    const uint32_t stg = sbase + (uint32_t)(cc % 3) * STAGE_SB;
    const int k0 = cc * 64;
#pragma unroll
    for (int i = 0; i < 4; i++) {
        int c = tid + i * 256;       // 0..1023
        int r = c >> 3, sg = c & 7;
        uint32_t dof = (uint32_t)(r * 144 + sg * 16);
        size_t ao = (size_t)(m0 + r) * K + k0 + sg * 8;
        size_t bo = (size_t)(n0 + r) * K + k0 + sg * 8;
        CP16(stg + dof, (const char*)(A + ao));
        CP16(stg + A_SB + dof, (const char*)(B + bo));
    }
    CPCOMMIT();
}

__device__ __forceinline__ void gemm_mainloop(
    const __half* A, const __half* B, const uint32_t sbase,
    int m0, int n0, int K, int tid, int lane, int wm, int wn,
    float acc[4][4][4])
{
    const int NCH = K >> 6;
    gemm_issue(A, B, sbase, m0, n0, K, 0, tid);
    gemm_issue(A, B, sbase, m0, n0, K, 1, tid);

    const uint32_t a_row  = (uint32_t)(wm * 64 + (lane & 15));
    const uint32_t a_koff = (uint32_t)((lane >> 4) * 8);
    const uint32_t b_row  = (uint32_t)(wn * 32 + (lane & 7) + ((lane >> 4) << 3));
    const uint32_t b_koff = (uint32_t)(((lane >> 3) & 1) * 8);

    for (int c = 0; c < NCH; c++) {
        CPWAIT1();
        __syncthreads();
        if (c + 2 < NCH) gemm_issue(A, B, sbase, m0, n0, K, c + 2, tid);
        else CPCOMMIT();

        const uint32_t stg = sbase + (uint32_t)(c % 3) * STAGE_SB;
#pragma unroll
        for (int ks = 0; ks < 4; ks++) {
            const uint32_t kofs = (uint32_t)(ks * 16);
            uint32_t a[4][4];
#pragma unroll
            for (int mt = 0; mt < 4; mt++) {
                uint32_t adr = stg + ((a_row + mt * 16) * LDS + kofs + a_koff) * 2;
                LDMX4(a[mt][0], a[mt][1], a[mt][2], a[mt][3], adr);
            }
            uint32_t b[2][4];
#pragma unroll
            for (int p = 0; p < 2; p++) {
                uint32_t adr = stg + A_SB
                             + ((b_row + p * 16) * LDS + kofs + b_koff) * 2;
                LDMX4(b[p][0], b[p][1], b[p][2], b[p][3], adr);
            }
#pragma unroll
            for (int mt = 0; mt < 4; mt++)
#pragma unroll
                for (int nt = 0; nt < 4; nt++) {
                    const int p = nt >> 1, hh = (nt & 1) * 2;
                    MMA16816(acc[mt][nt], a[mt], b[p][hh], b[p][hh + 1]);
                }
        }
    }
}

// ---------------------------------------------------------------------------
// Out-projection GEMM: writes fp32 C + bias
// ---------------------------------------------------------------------------
__global__ __launch_bounds__(256, 2) void gemm_fp16(
    const __half* __restrict__ A, const __half* __restrict__ B,
    const float* __restrict__ bias, float* __restrict__ C, int N, int K)
{
    extern __shared__ char dsm[];
    __shared__ float sBias[128];

    const int tid  = threadIdx.x;
    const int lane = tid & 31;
    const int wid  = tid >> 5;
    const int wm   = wid >> 2;
    const int wn   = wid & 3;
    const int m0 = blockIdx.y * 128, n0 = blockIdx.x * 128;
    const uint32_t sbase = smem_u32(dsm);

    if (tid < 128) sBias[tid] = bias[n0 + tid];

    float acc[4][4][4];
#pragma unroll
    for (int mt = 0; mt < 4; mt++)
#pragma unroll
        for (int nt = 0; nt < 4; nt++)
#pragma unroll
            for (int r = 0; r < 4; r++) acc[mt][nt][r] = 0.0f;

    gemm_mainloop(A, B, sbase, m0, n0, K, tid, lane, wm, wn, acc);

    const int erow = wm * 64 + (lane >> 2);
    const int ecol = wn * 32 + (lane & 3) * 2;
#pragma unroll
    for (int mt = 0; mt < 4; mt++) {
#pragma unroll
        for (int nt = 0; nt < 4; nt++) {
            const int cc = ecol + nt * 8;
            const float b0 = sBias[cc], b1 = sBias[cc + 1];
            float* p0 = C + (size_t)(m0 + erow + mt * 16) * N + n0 + cc;
            float* p1 = C + (size_t)(m0 + erow + mt * 16 + 8) * N + n0 + cc;
            float2 v0 = {acc[mt][nt][0] + b0, acc[mt][nt][1] + b1};
            float2 v1 = {acc[mt][nt][2] + b0, acc[mt][nt][3] + b1};
            *(float2*)p0 = v0;
            *(float2*)p1 = v1;
        }
    }
}

// ---------------------------------------------------------------------------
// QKV GEMM with fused RoPE/scale epilogue (table trig). Q/K/V all plain fp16.
// N-tile (128 cols) = one (slot, head): slot = bx/16, head = bx%16.
// ---------------------------------------------------------------------------
#define CT_STRIDE 132   // fp32 stage-tile row stride

__global__ __launch_bounds__(256, 2) void gemm_qkv(
    const __half* __restrict__ A, const __half* __restrict__ B,
    const float* __restrict__ bias, const float* __restrict__ rope,
    __half* __restrict__ Qp, __half* __restrict__ Kp,
    __half* __restrict__ Vp, int K)
{
    extern __shared__ char dsm[];
    __shared__ float sBias[128];

    const int tid  = threadIdx.x;
    const int lane = tid & 31;
    const int wid  = tid >> 5;
    const int wm   = wid >> 2;
    const int wn   = wid & 3;
    const int m0 = blockIdx.y * 128, n0 = blockIdx.x * 128;
    const uint32_t sbase = smem_u32(dsm);

    if (tid < 128) sBias[tid] = bias[n0 + tid];

    float acc[4][4][4];
#pragma unroll
    for (int mt = 0; mt < 4; mt++)
#pragma unroll
        for (int nt = 0; nt < 4; nt++)
#pragma unroll
            for (int r = 0; r < 4; r++) acc[mt][nt][r] = 0.0f;

    gemm_mainloop(A, B, sbase, m0, n0, K, tid, lane, wm, wn, acc);

    // ---- stage acc + bias into smem fp32 tile (reuse pipeline smem) ----
    __syncthreads();
    float* ctile = (float*)dsm;
    const int erow = wm * 64 + (lane >> 2);
    const int ecol = wn * 32 + (lane & 3) * 2;
#pragma unroll
    for (int mt = 0; mt < 4; mt++) {
#pragma unroll
        for (int nt = 0; nt < 4; nt++) {
            const int cc = ecol + nt * 8;
            const float b0 = sBias[cc], b1 = sBias[cc + 1];
            ctile[(erow + mt * 16) * CT_STRIDE + cc]     = acc[mt][nt][0] + b0;
            ctile[(erow + mt * 16) * CT_STRIDE + cc + 1] = acc[mt][nt][1] + b1;
            ctile[(erow + mt * 16 + 8) * CT_STRIDE + cc]     = acc[mt][nt][2] + b0;
            ctile[(erow + mt * 16 + 8) * CT_STRIDE + cc + 1] = acc[mt][nt][3] + b1;
        }
    }
    __syncthreads();

    // ---- RoPE / store (trig from table) ----
    const int slot = blockIdx.x >> 4;      // 0=Q, 1=K, 2=V
    const int h    = blockIdx.x & 15;
    const float scale = 0.08838834764831845f;

#pragma unroll 4
    for (int i = 0; i < 32; i++) {
        int idx = tid + i * 256;           // 0..8191
        int r = idx >> 6, j = idx & 63;
        int row = m0 + r;
        int b = row >> 11;                 // / SEQ
        int s = row & (SEQ - 1);
        size_t dst = ((size_t)(b * HEADS + h) * SEQ + s) * HDIM + j;
        float v1 = ctile[r * CT_STRIDE + j];
        float v2 = ctile[r * CT_STRIDE + j + 64];
        if (slot == 2) {
            Vp[dst]      = __float2half_rn(v1);
            Vp[dst + 64] = __float2half_rn(v2);
        } else {
            float2 cssn = *(const float2*)(rope + (size_t)(s * 64 + j) * 2);
            float r1 = v1 * cssn.x - v2 * cssn.y;
            float r2 = v1 * cssn.y + v2 * cssn.x;
            if (slot == 0) {
                Qp[dst]      = __float2half_rn(r1 * scale);
                Qp[dst + 64] = __float2half_rn(r2 * scale);
            } else {
                Kp[dst]      = __float2half_rn(r1);
                Kp[dst + 64] = __float2half_rn(r2);
            }
        }
    }
}

// ---------------------------------------------------------------------------
// Flash attention: Q/K/V all plain fp16, causal.
// 128 threads (4 warps x 16 q-rows), 64x64 KV tiles, D=128, 3 CTAs/SM.
// smem tiles: Q, K, V
// ---------------------------------------------------------------------------
#define FL_STRIDE_B 272                  // 136 fp16 per smem row
#define FL_TILE (64 * FL_STRIDE_B)       // 17408 B
#define FLASH_SMEM (3 * FL_TILE)         // 52224 B -> 3 CTAs/SM (smem-wise 4)

__global__ __launch_bounds__(128, 3) void flash_mma(
    const __half* __restrict__ Qp, const __half* __restrict__ Kp,
    const __half* __restrict__ Vp,
    __half* __restrict__ ctx)
{
    extern __shared__ char fsm[];
    const int qt = gridDim.x - 1 - blockIdx.x;   // heavy tiles first
    const int bh = blockIdx.y;
    const int tid = threadIdx.x, lane = tid & 31, w = tid >> 5;
    const int q0 = qt * 64;
    const uint32_t sb = smem_u32(fsm);

    {
        const size_t qo = ((size_t)bh * SEQ + q0) * HDIM;
#pragma unroll
        for (int i = 0; i < 8; i++) {
            int c = tid + i * 128;
            int r = c >> 4, sg = c & 15;
            *(uint4*)(fsm + r * FL_STRIDE_B + sg * 16) =
                *(const uint4*)(Qp + qo + r * HDIM + sg * 8);
        }
    }

    float m0v = -1e30f, m1v = -1e30f, l0v = 0.0f, l1v = 0.0f;
    float o[16][4];
#pragma unroll
    for (int nt = 0; nt < 16; nt++)
#pragma unroll
        for (int r = 0; r < 4; r++) o[nt][r] = 0.0f;

    const uint32_t a_row  = (uint32_t)(w * 16 + (lane & 15));
    const uint32_t a_koff = (uint32_t)((lane >> 4) * 8);
    const uint32_t b_row  = (uint32_t)((lane & 7) + ((lane >> 4) << 3));
    const uint32_t b_koff = (uint32_t)(((lane >> 3) & 1) * 8);
    const uint32_t v_row  = (uint32_t)(lane & 15);
    const uint32_t v_coff = (uint32_t)((lane >> 4) * 8);

    for (int kt = 0; kt <= qt; kt++) {
        __syncthreads();

        const size_t ko = ((size_t)bh * SEQ + kt * 64) * HDIM;
#pragma unroll
        for (int i = 0; i < 8; i++) {
            int c = tid + i * 128;
            int r = c >> 4, sg = c & 15;
            uint32_t dof = (uint32_t)(r * FL_STRIDE_B + sg * 16);
            size_t so = ko + r * HDIM + sg * 8;
            CP16(sb + 1 * FL_TILE + dof, (const char*)(Kp + so));
        }
        CPCOMMIT();
#pragma unroll
        for (int i = 0; i < 8; i++) {
            int c = tid + i * 128;
            int r = c >> 4, sg = c & 15;
            uint32_t dof = (uint32_t)(r * FL_STRIDE_B + sg * 16);
            size_t so = ko + r * HDIM + sg * 8;
            CP16(sb + 2 * FL_TILE + dof, (const char*)(Vp + so));
        }
        CPCOMMIT();

        CPWAIT1();
        __syncthreads();

        float s[8][4];
#pragma unroll
        for (int nt = 0; nt < 8; nt++)
#pragma unroll
            for (int r = 0; r < 4; r++) s[nt][r] = 0.0f;

#pragma unroll
        for (int ks = 0; ks < 8; ks++) {
            uint32_t q[4];
            uint32_t qadr = sb + a_row * FL_STRIDE_B + (ks * 16 + a_koff) * 2;
            LDMX4(q[0], q[1], q[2], q[3], qadr);
            uint32_t kf[4][4];
#pragma unroll
            for (int np = 0; np < 4; np++) {
                uint32_t kadr = sb + 1 * FL_TILE
                              + (np * 16 + b_row) * FL_STRIDE_B
                              + (ks * 16 + b_koff) * 2;
                LDMX4(kf[np][0], kf[np][1], kf[np][2], kf[np][3], kadr);
            }
#pragma unroll
            for (int np = 0; np < 4; np++) {
                MMA16816(s[2*np],   q, kf[np][0], kf[np][1]);
                MMA16816(s[2*np+1], q, kf[np][2], kf[np][3]);
            }
        }

        if (kt == qt) {
            const int r0 = w * 16 + (lane >> 2);
            const int r1 = r0 + 8;
#pragma unroll
            for (int nt = 0; nt < 8; nt++) {
                const int cb = nt * 8 + (lane & 3) * 2;
                if (cb     > r0) s[nt][0] = -1e30f;
                if (cb + 1 > r0) s[nt][1] = -1e30f;
                if (cb     > r1) s[nt][2] = -1e30f;
                if (cb + 1 > r1) s[nt][3] = -1e30f;
            }
        }

        float mx0 = -1e30f, mx1 = -1e30f;
#pragma unroll
        for (int nt = 0; nt < 8; nt++) {
            mx0 = fmaxf(mx0, fmaxf(s[nt][0], s[nt][1]));
            mx1 = fmaxf(mx1, fmaxf(s[nt][2], s[nt][3]));
        }
        mx0 = fmaxf(mx0, __shfl_xor_sync(0xffffffffu, mx0, 1));
        mx0 = fmaxf(mx0, __shfl_xor_sync(0xffffffffu, mx0, 2));
        mx1 = fmaxf(mx1, __shfl_xor_sync(0xffffffffu, mx1, 1));
        mx1 = fmaxf(mx1, __shfl_xor_sync(0xffffffffu, mx1, 2));

        float mn0 = fmaxf(m0v, mx0), mn1 = fmaxf(m1v, mx1);
        float sf0 = __expf(m0v - mn0), sf1 = __expf(m1v - mn1);
        m0v = mn0; m1v = mn1;

        float ls0 = 0.0f, ls1 = 0.0f;
#pragma unroll
        for (int nt = 0; nt < 8; nt++) {
            s[nt][0] = __expf(s[nt][0] - mn0); ls0 += s[nt][0];
            s[nt][1] = __expf(s[nt][1] - mn0); ls0 += s[nt][1];
            s[nt][2] = __expf(s[nt][2] - mn1); ls1 += s[nt][2];
            s[nt][3] = __expf(s[nt][3] - mn1); ls1 += s[nt][3];
        }
        ls0 += __shfl_xor_sync(0xffffffffu, ls0, 1);
        ls0 += __shfl_xor_sync(0xffffffffu, ls0, 2);
        ls1 += __shfl_xor_sync(0xffffffffu, ls1, 1);
        ls1 += __shfl_xor_sync(0xffffffffu, ls1, 2);
        l0v = l0v * sf0 + ls0;
        l1v = l1v * sf1 + ls1;
#pragma unroll
        for (int nt = 0; nt < 16; nt++) {
            o[nt][0] *= sf0; o[nt][1] *= sf0;
            o[nt][2] *= sf1; o[nt][3] *= sf1;
        }

        uint32_t ph[4][4];
#pragma unroll
        for (int k2 = 0; k2 < 4; k2++) {
            ph[k2][0] = cvt_plain_h(s[2*k2][0],   s[2*k2][1]);
            ph[k2][1] = cvt_plain_h(s[2*k2][2],   s[2*k2][3]);
            ph[k2][2] = cvt_plain_h(s[2*k2+1][0], s[2*k2+1][1]);
            ph[k2][3] = cvt_plain_h(s[2*k2+1][2], s[2*k2+1][3]);
        }

        CPWAIT0();
        __syncthreads();

#pragma unroll
        for (int k2 = 0; k2 < 4; k2++) {
#pragma unroll
            for (int npp = 0; npp < 4; npp++) {
                const int np0 = 2 * npp, np1 = 2 * npp + 1;
                uint32_t vh0[4], vh1[4];
                uint32_t va0 = sb + 2 * FL_TILE
                             + (k2 * 16 + v_row) * FL_STRIDE_B
                             + (np0 * 16 + v_coff) * 2;
                uint32_t va1 = va0 + 32;
                LDMT4(vh0[0], vh0[1], vh0[2], vh0[3], va0);
                LDMT4(vh1[0], vh1[1], vh1[2], vh1[3], va1);
                MMA16816(o[2*np0],   ph[k2], vh0[0], vh0[1]);
                MMA16816(o[2*np0+1], ph[k2], vh0[2], vh0[3]);
                MMA16816(o[2*np1],   ph[k2], vh1[0], vh1[1]);
                MMA16816(o[2*np1+1], ph[k2], vh1[2], vh1[3]);
            }
        }
    }

    const float inv0 = 1.0f / l0v, inv1 = 1.0f / l1v;
    const int b = bh >> 4, h = bh & 15;
    const int gr0 = q0 + w * 16 + (lane >> 2);
    const size_t ro0 = (size_t)(b * SEQ + gr0) * EMB + h * HDIM;
    const size_t ro1 = (size_t)(b * SEQ + gr0 + 8) * EMB + h * HDIM;
#pragma unroll
    for (int nt = 0; nt < 16; nt++) {
        const int col = nt * 8 + (lane & 3) * 2;
        *(uint32_t*)(ctx + ro0 + col) = cvt_plain_h(o[nt][0] * inv0, o[nt][1] * inv0);
        *(uint32_t*)(ctx + ro1 + col) = cvt_plain_h(o[nt][2] * inv1, o[nt][3] * inv1);
    }
}

// ---------------------------------------------------------------------------
extern "C" void kernel_launch(void* const* d_in, const int* in_sizes, int n_in,
                              void* d_out, int out_size)
{
    const float* x      = (const float*)d_in[0];
    const float* wqkv_w = (const float*)d_in[1];
    const float* wqkv_b = (const float*)d_in[2];
    const float* out_w  = (const float*)d_in[3];
    const float* out_b  = (const float*)d_in[4];
    float* out = (float*)d_out;

    __half *x16, *w16, *o16w;
    __half *qp, *kp, *vp, *c16;
    float* rope;
    cudaGetSymbolAddress((void**)&x16, g_x16);
    cudaGetSymbolAddress((void**)&w16, g_w16);
    cudaGetSymbolAddress((void**)&o16w, g_o16w);
    cudaGetSymbolAddress((void**)&qp, g_qp);
    cudaGetSymbolAddress((void**)&kp, g_kp);
    cudaGetSymbolAddress((void**)&vp, g_vp);
    cudaGetSymbolAddress((void**)&c16, g_c16);
    cudaGetSymbolAddress((void**)&rope, g_rope);

    cudaFuncSetAttribute(gemm_fp16, cudaFuncAttributeMaxDynamicSharedMemorySize, GEMM_SMEM);
    cudaFuncSetAttribute(gemm_qkv, cudaFuncAttributeMaxDynamicSharedMemorySize, GEMM_SMEM);
    cudaFuncSetAttribute(flash_mma, cudaFuncAttributeMaxDynamicSharedMemorySize, FLASH_SMEM);

    int n4;
    n4 = MROWS * EMB / 4;
    cvt_f32_h<<<(n4 + 255) / 256, 256>>>((const float4*)x, (uint2*)x16, n4);
    n4 = THREE_E * EMB / 4;
    cvt_f32_h<<<(n4 + 255) / 256, 256>>>((const float4*)wqkv_w, (uint2*)w16, n4);
    n4 = EMB * EMB / 4;
    cvt_f32_h<<<(n4 + 255) / 256, 256>>>((const float4*)out_w, (uint2*)o16w, n4);
    rope_table<<<(SEQ * 64 + 255) / 256, 256>>>(rope);

    // QKV projection with fused RoPE epilogue
    dim3 g1(THREE_E / 128, MROWS / 128);
    gemm_qkv<<<g1, 256, GEMM_SMEM>>>(x16, w16, wqkv_b, rope, qp, kp, vp, EMB);

    // attention
    dim3 g2(SEQ / 64, NBH);
    flash_mma<<<g2, 128, FLASH_SMEM>>>(qp, kp, vp, c16);

    // output projection
    dim3 g3(EMB / 128, MROWS / 128);
    gemm_fp16<<<g3, 256, GEMM_SMEM>>>(c16, o16w, out_b, out, EMB, EMB);
}

// round 16
// speedup vs baseline: 1.1747x; 1.0069x over previous
#include <cuda_runtime.h>
#include <cuda_fp16.h>
#include <math.h>
#include <stdint.h>

#define BATCH 2
#define SEQ   2048
#define EMB   2048
#define HEADS 16
#define HDIM  128
#define THREE_E 6144
#define MROWS (BATCH*SEQ)     // 4096
#define NBH   (BATCH*HEADS)   // 32

// ---------------- scratch (__device__ globals; no cudaMalloc) ----------------
__device__ __half g_x16[(size_t)MROWS * EMB];                    // x plain fp16
__device__ __half g_w16[(size_t)THREE_E * EMB];                  // wqkv plain fp16
__device__ __half g_o16w[(size_t)EMB * EMB];                     // out_w plain fp16
__device__ __half g_qp[(size_t)NBH*SEQ*HDIM];                    // Q plain fp16
__device__ __half g_kp[(size_t)NBH*SEQ*HDIM];                    // K plain fp16
__device__ __half g_vp[(size_t)NBH*SEQ*HDIM];                    // V plain fp16
__device__ __half g_c16[(size_t)MROWS * EMB];                    // ctx plain fp16
__device__ float  g_rope[(size_t)SEQ * 64 * 2];                  // (cos,sin) table

// ---------------- PTX helpers ----------------
__device__ __forceinline__ uint32_t smem_u32(const void* p) {
    uint32_t a;
    asm("{ .reg .u64 t; cvta.to.shared.u64 t, %1; cvt.u32.u64 %0, t; }"
        : "=r"(a) : "l"(p));
    return a;
}
__device__ __forceinline__ uint32_t cvt_plain_h(float f0, float f1) {
    uint32_t h;
    asm("cvt.rn.f16x2.f32 %0, %1, %2;" : "=r"(h) : "f"(f1), "f"(f0));
    return h;
}
#define LDMX4(r0, r1, r2, r3, addr) \
    asm volatile("ldmatrix.sync.aligned.m8n8.x4.shared.b16 {%0,%1,%2,%3}, [%4];" \
        : "=r"(r0), "=r"(r1), "=r"(r2), "=r"(r3) : "r"(addr))
#define LDMT4(r0, r1, r2, r3, addr) \
    asm volatile("ldmatrix.sync.aligned.m8n8.x4.trans.shared.b16 {%0,%1,%2,%3}, [%4];" \
        : "=r"(r0), "=r"(r1), "=r"(r2), "=r"(r3) : "r"(addr))
#define MMA16816(d, a, b0, b1) \
    asm volatile("mma.sync.aligned.m16n8k16.row.col.f32.f16.f16.f32 " \
        "{%0,%1,%2,%3}, {%4,%5,%6,%7}, {%8,%9}, {%0,%1,%2,%3};" \
        : "+f"((d)[0]), "+f"((d)[1]), "+f"((d)[2]), "+f"((d)[3]) \
        : "r"((a)[0]), "r"((a)[1]), "r"((a)[2]), "r"((a)[3]), "r"(b0), "r"(b1))
#define CP16(dst, src) \
    asm volatile("cp.async.cg.shared.global [%0], [%1], 16;" :: "r"(dst), "l"(src))
#define CPCOMMIT() asm volatile("cp.async.commit_group;" ::: "memory")
#define CPWAIT0()  asm volatile("cp.async.wait_group 0;" ::: "memory")
#define CPWAIT1()  asm volatile("cp.async.wait_group 1;" ::: "memory")

// ---------------------------------------------------------------------------
// Prep: fp32 -> plain fp16 ; RoPE table
// ---------------------------------------------------------------------------
__global__ void cvt_f32_h(const float4* __restrict__ in,
                          uint2* __restrict__ o16, int n4)
{
    int i = blockIdx.x * blockDim.x + threadIdx.x;
    if (i >= n4) return;
    float4 v = in[i];
    o16[i] = make_uint2(cvt_plain_h(v.x, v.y), cvt_plain_h(v.z, v.w));
}

__global__ void rope_table(float* __restrict__ tab)
{
    int idx = blockIdx.x * blockDim.x + threadIdx.x;   // SEQ*64
    if (idx >= SEQ * 64) return;
    int j = idx & 63, s = idx >> 6;
    float inv = powf(10000.0f, -(float)j / 64.0f);
    float sn, cs;
    sincosf((float)s * inv, &sn, &cs);
    tab[idx * 2]     = cs;
    tab[idx * 2 + 1] = sn;
}

// ---------------------------------------------------------------------------
// Shared GEMM mainloop config: BM=BN=128, BK=64, 256 thr, 3-stage, 2 CTAs/SM
// ---------------------------------------------------------------------------
#define LDS 72                       // 64 fp16 data + 8 pad per row (144 B)
#define A_SB (128 * LDS * 2)         // 18432 B
#define STAGE_SB (2 * A_SB)          // 36864 B (A + B)
#define GEMM_SMEM (3 * STAGE_SB)     // 110592 B  -> 2 CTAs/SM

__device__ __forceinline__ void gemm_issue(
    const __half* A, const __half* B,
    uint32_t sbase, int m0, int n0, int K, int cc, int tid)
{
    const uint32_t stg = sbase + (uint32_t)(cc % 3) * STAGE_SB;
    const int k0 = cc * 64;
#pragma unroll
    for (int i = 0; i < 4; i++) {
        int c = tid + i * 256;       // 0..1023
        int r = c >> 3, sg = c & 7;
        uint32_t dof = (uint32_t)(r * 144 + sg * 16);
        size_t ao = (size_t)(m0 + r) * K + k0 + sg * 8;
        size_t bo = (size_t)(n0 + r) * K + k0 + sg * 8;
        CP16(stg + dof, (const char*)(A + ao));
        CP16(stg + A_SB + dof, (const char*)(B + bo));
    }
    CPCOMMIT();
}

__device__ __forceinline__ void gemm_mainloop(
    const __half* A, const __half* B, const uint32_t sbase,
    int m0, int n0, int K, int tid, int lane, int wm, int wn,
    float acc[4][4][4])
{
    const int NCH = K >> 6;
    gemm_issue(A, B, sbase, m0, n0, K, 0, tid);
    gemm_issue(A, B, sbase, m0, n0, K, 1, tid);

    const uint32_t a_row  = (uint32_t)(wm * 64 + (lane & 15));
    const uint32_t a_koff = (uint32_t)((lane >> 4) * 8);
    const uint32_t b_row  = (uint32_t)(wn * 32 + (lane & 7) + ((lane >> 4) << 3));
    const uint32_t b_koff = (uint32_t)(((lane >> 3) & 1) * 8);

    for (int c = 0; c < NCH; c++) {
        CPWAIT1();
        __syncthreads();
        if (c + 2 < NCH) gemm_issue(A, B, sbase, m0, n0, K, c + 2, tid);
        else CPCOMMIT();

        const uint32_t stg = sbase + (uint32_t)(c % 3) * STAGE_SB;
#pragma unroll
        for (int ks = 0; ks < 4; ks++) {
            const uint32_t kofs = (uint32_t)(ks * 16);
            uint32_t a[4][4];
#pragma unroll
            for (int mt = 0; mt < 4; mt++) {
                uint32_t adr = stg + ((a_row + mt * 16) * LDS + kofs + a_koff) * 2;
                LDMX4(a[mt][0], a[mt][1], a[mt][2], a[mt][3], adr);
            }
            uint32_t b[2][4];
#pragma unroll
            for (int p = 0; p < 2; p++) {
                uint32_t adr = stg + A_SB
                             + ((b_row + p * 16) * LDS + kofs + b_koff) * 2;
                LDMX4(b[p][0], b[p][1], b[p][2], b[p][3], adr);
            }
#pragma unroll
            for (int mt = 0; mt < 4; mt++)
#pragma unroll
                for (int nt = 0; nt < 4; nt++) {
                    const int p = nt >> 1, hh = (nt & 1) * 2;
                    MMA16816(acc[mt][nt], a[mt], b[p][hh], b[p][hh + 1]);
                }
        }
    }
}

// ---------------------------------------------------------------------------
// Out-projection GEMM: writes fp32 C + bias
// ---------------------------------------------------------------------------
__global__ __launch_bounds__(256, 2) void gemm_fp16(
    const __half* __restrict__ A, const __half* __restrict__ B,
    const float* __restrict__ bias, float* __restrict__ C, int N, int K)
{
    extern __shared__ char dsm[];
    __shared__ float sBias[128];

    const int tid  = threadIdx.x;
    const int lane = tid & 31;
    const int wid  = tid >> 5;
    const int wm   = wid >> 2;
    const int wn   = wid & 3;
    const int m0 = blockIdx.y * 128, n0 = blockIdx.x * 128;
    const uint32_t sbase = smem_u32(dsm);

    if (tid < 128) sBias[tid] = bias[n0 + tid];

    float acc[4][4][4];
#pragma unroll
    for (int mt = 0; mt < 4; mt++)
#pragma unroll
        for (int nt = 0; nt < 4; nt++)
#pragma unroll
            for (int r = 0; r < 4; r++) acc[mt][nt][r] = 0.0f;

    gemm_mainloop(A, B, sbase, m0, n0, K, tid, lane, wm, wn, acc);

    const int erow = wm * 64 + (lane >> 2);
    const int ecol = wn * 32 + (lane & 3) * 2;
#pragma unroll
    for (int mt = 0; mt < 4; mt++) {
#pragma unroll
        for (int nt = 0; nt < 4; nt++) {
            const int cc = ecol + nt * 8;
            const float b0 = sBias[cc], b1 = sBias[cc + 1];
            float* p0 = C + (size_t)(m0 + erow + mt * 16) * N + n0 + cc;
            float* p1 = C + (size_t)(m0 + erow + mt * 16 + 8) * N + n0 + cc;
            float2 v0 = {acc[mt][nt][0] + b0, acc[mt][nt][1] + b1};
            float2 v1 = {acc[mt][nt][2] + b0, acc[mt][nt][3] + b1};
            *(float2*)p0 = v0;
            *(float2*)p1 = v1;
        }
    }
}

// ---------------------------------------------------------------------------
// QKV GEMM with fused RoPE/scale epilogue (table trig). Q/K/V all plain fp16.
// N-tile (128 cols) = one (slot, head): slot = bx/16, head = bx%16.
// ---------------------------------------------------------------------------
#define CT_STRIDE 132   // fp32 stage-tile row stride

__global__ __launch_bounds__(256, 2) void gemm_qkv(
    const __half* __restrict__ A, const __half* __restrict__ B,
    const float* __restrict__ bias, const float* __restrict__ rope,
    __half* __restrict__ Qp, __half* __restrict__ Kp,
    __half* __restrict__ Vp, int K)
{
    extern __shared__ char dsm[];
    __shared__ float sBias[128];

    const int tid  = threadIdx.x;
    const int lane = tid & 31;
    const int wid  = tid >> 5;
    const int wm   = wid >> 2;
    const int wn   = wid & 3;
    const int m0 = blockIdx.y * 128, n0 = blockIdx.x * 128;
    const uint32_t sbase = smem_u32(dsm);

    if (tid < 128) sBias[tid] = bias[n0 + tid];

    float acc[4][4][4];
#pragma unroll
    for (int mt = 0; mt < 4; mt++)
#pragma unroll
        for (int nt = 0; nt < 4; nt++)
#pragma unroll
            for (int r = 0; r < 4; r++) acc[mt][nt][r] = 0.0f;

    gemm_mainloop(A, B, sbase, m0, n0, K, tid, lane, wm, wn, acc);

    // ---- stage acc + bias into smem fp32 tile (reuse pipeline smem) ----
    __syncthreads();
    float* ctile = (float*)dsm;
    const int erow = wm * 64 + (lane >> 2);
    const int ecol = wn * 32 + (lane & 3) * 2;
#pragma unroll
    for (int mt = 0; mt < 4; mt++) {
#pragma unroll
        for (int nt = 0; nt < 4; nt++) {
            const int cc = ecol + nt * 8;
            const float b0 = sBias[cc], b1 = sBias[cc + 1];
            ctile[(erow + mt * 16) * CT_STRIDE + cc]     = acc[mt][nt][0] + b0;
            ctile[(erow + mt * 16) * CT_STRIDE + cc + 1] = acc[mt][nt][1] + b1;
            ctile[(erow + mt * 16 + 8) * CT_STRIDE + cc]     = acc[mt][nt][2] + b0;
            ctile[(erow + mt * 16 + 8) * CT_STRIDE + cc + 1] = acc[mt][nt][3] + b1;
        }
    }
    __syncthreads();

    // ---- RoPE / store (trig from table) ----
    const int slot = blockIdx.x >> 4;      // 0=Q, 1=K, 2=V
    const int h    = blockIdx.x & 15;
    const float scale = 0.08838834764831845f;

#pragma unroll 4
    for (int i = 0; i < 32; i++) {
        int idx = tid + i * 256;           // 0..8191
        int r = idx >> 6, j = idx & 63;
        int row = m0 + r;
        int b = row >> 11;                 // / SEQ
        int s = row & (SEQ - 1);
        size_t dst = ((size_t)(b * HEADS + h) * SEQ + s) * HDIM + j;
        float v1 = ctile[r * CT_STRIDE + j];
        float v2 = ctile[r * CT_STRIDE + j + 64];
        if (slot == 2) {
            Vp[dst]      = __float2half_rn(v1);
            Vp[dst + 64] = __float2half_rn(v2);
        } else {
            float2 cssn = *(const float2*)(rope + (size_t)(s * 64 + j) * 2);
            float r1 = v1 * cssn.x - v2 * cssn.y;
            float r2 = v1 * cssn.y + v2 * cssn.x;
            if (slot == 0) {
                Qp[dst]      = __float2half_rn(r1 * scale);
                Qp[dst + 64] = __float2half_rn(r2 * scale);
            } else {
                Kp[dst]      = __float2half_rn(r1);
                Kp[dst + 64] = __float2half_rn(r2);
            }
        }
    }
}

// ---------------------------------------------------------------------------
// Flash attention: Q/K/V plain fp16, causal, double-buffered KV prefetch.
// 128 threads (4 warps x 16 q-rows), 64x64 KV tiles, D=128, 2 CTAs/SM.
// smem: Q, K0, V0, K1, V1
// ---------------------------------------------------------------------------
#define FL_STRIDE_B 272                  // 136 fp16 per smem row
#define FL_TILE (64 * FL_STRIDE_B)       // 17408 B
#define FLASH_SMEM (5 * FL_TILE)         // 87040 B -> 2 CTAs/SM

__global__ __launch_bounds__(128, 2) void flash_mma(
    const __half* __restrict__ Qp, const __half* __restrict__ Kp,
    const __half* __restrict__ Vp,
    __half* __restrict__ ctx)
{
    extern __shared__ char fsm[];
    const int qt = gridDim.x - 1 - blockIdx.x;   // heavy tiles first
    const int bh = blockIdx.y;
    const int tid = threadIdx.x, lane = tid & 31, w = tid >> 5;
    const int q0 = qt * 64;
    const uint32_t sb = smem_u32(fsm);

    // Load Q tile (regular stores; visible after first barrier)
    {
        const size_t qo = ((size_t)bh * SEQ + q0) * HDIM;
#pragma unroll
        for (int i = 0; i < 8; i++) {
            int c = tid + i * 128;
            int r = c >> 4, sg = c & 15;
            *(uint4*)(fsm + r * FL_STRIDE_B + sg * 16) =
                *(const uint4*)(Qp + qo + r * HDIM + sg * 8);
        }
    }

    // Prefetch KV for tiles 0 and 1 (one commit-group per tile, K+V together)
    const size_t bho = (size_t)bh * SEQ * HDIM;
    {
#pragma unroll
        for (int i = 0; i < 8; i++) {
            int c = tid + i * 128;
            int r = c >> 4, sg = c & 15;
            uint32_t dof = (uint32_t)(r * FL_STRIDE_B + sg * 16);
            size_t so = bho + r * HDIM + sg * 8;     // tile 0
            CP16(sb + 1 * FL_TILE + dof, (const char*)(Kp + so));
            CP16(sb + 2 * FL_TILE + dof, (const char*)(Vp + so));
        }
        CPCOMMIT();
        if (qt >= 1) {
#pragma unroll
            for (int i = 0; i < 8; i++) {
                int c = tid + i * 128;
                int r = c >> 4, sg = c & 15;
                uint32_t dof = (uint32_t)(r * FL_STRIDE_B + sg * 16);
                size_t so = bho + (size_t)64 * HDIM + r * HDIM + sg * 8;  // tile 1
                CP16(sb + 3 * FL_TILE + dof, (const char*)(Kp + so));
                CP16(sb + 4 * FL_TILE + dof, (const char*)(Vp + so));
            }
        }
        CPCOMMIT();
    }

    float m0v = -1e30f, m1v = -1e30f, l0v = 0.0f, l1v = 0.0f;
    float o[16][4];
#pragma unroll
    for (int nt = 0; nt < 16; nt++)
#pragma unroll
        for (int r = 0; r < 4; r++) o[nt][r] = 0.0f;

    const uint32_t a_row  = (uint32_t)(w * 16 + (lane & 15));
    const uint32_t a_koff = (uint32_t)((lane >> 4) * 8);
    const uint32_t b_row  = (uint32_t)((lane & 7) + ((lane >> 4) << 3));
    const uint32_t b_koff = (uint32_t)(((lane >> 3) & 1) * 8);
    const uint32_t v_row  = (uint32_t)(lane & 15);
    const uint32_t v_coff = (uint32_t)((lane >> 4) * 8);

    for (int kt = 0; kt <= qt; kt++) {
        CPWAIT1();          // tile kt resident; tile kt+1 may still be in flight
        __syncthreads();    // (also covers Q stores on iter 0)

        const uint32_t kb = sb + (uint32_t)(1 + 2 * (kt & 1)) * FL_TILE;
        const uint32_t vb = kb + FL_TILE;

        float s[8][4];
#pragma unroll
        for (int nt = 0; nt < 8; nt++)
#pragma unroll
            for (int r = 0; r < 4; r++) s[nt][r] = 0.0f;

#pragma unroll
        for (int ks = 0; ks < 8; ks++) {
            uint32_t q[4];
            uint32_t qadr = sb + a_row * FL_STRIDE_B + (ks * 16 + a_koff) * 2;
            LDMX4(q[0], q[1], q[2], q[3], qadr);
            uint32_t kf[4][4];
#pragma unroll
            for (int np = 0; np < 4; np++) {
                uint32_t kadr = kb + (np * 16 + b_row) * FL_STRIDE_B
                              + (ks * 16 + b_koff) * 2;
                LDMX4(kf[np][0], kf[np][1], kf[np][2], kf[np][3], kadr);
            }
#pragma unroll
            for (int np = 0; np < 4; np++) {
                MMA16816(s[2*np],   q, kf[np][0], kf[np][1]);
                MMA16816(s[2*np+1], q, kf[np][2], kf[np][3]);
            }
        }

        if (kt == qt) {
            const int r0 = w * 16 + (lane >> 2);
            const int r1 = r0 + 8;
#pragma unroll
            for (int nt = 0; nt < 8; nt++) {
                const int cb = nt * 8 + (lane & 3) * 2;
                if (cb     > r0) s[nt][0] = -1e30f;
                if (cb + 1 > r0) s[nt][1] = -1e30f;
                if (cb     > r1) s[nt][2] = -1e30f;
                if (cb + 1 > r1) s[nt][3] = -1e30f;
            }
        }

        float mx0 = -1e30f, mx1 = -1e30f;
#pragma unroll
        for (int nt = 0; nt < 8; nt++) {
            mx0 = fmaxf(mx0, fmaxf(s[nt][0], s[nt][1]));
            mx1 = fmaxf(mx1, fmaxf(s[nt][2], s[nt][3]));
        }
        mx0 = fmaxf(mx0, __shfl_xor_sync(0xffffffffu, mx0, 1));
        mx0 = fmaxf(mx0, __shfl_xor_sync(0xffffffffu, mx0, 2));
        mx1 = fmaxf(mx1, __shfl_xor_sync(0xffffffffu, mx1, 1));
        mx1 = fmaxf(mx1, __shfl_xor_sync(0xffffffffu, mx1, 2));

        float mn0 = fmaxf(m0v, mx0), mn1 = fmaxf(m1v, mx1);
        float sf0 = __expf(m0v - mn0), sf1 = __expf(m1v - mn1);
        m0v = mn0; m1v = mn1;

        float ls0 = 0.0f, ls1 = 0.0f;
#pragma unroll
        for (int nt = 0; nt < 8; nt++) {
            s[nt][0] = __expf(s[nt][0] - mn0); ls0 += s[nt][0];
            s[nt][1] = __expf(s[nt][1] - mn0); ls0 += s[nt][1];
            s[nt][2] = __expf(s[nt][2] - mn1); ls1 += s[nt][2];
            s[nt][3] = __expf(s[nt][3] - mn1); ls1 += s[nt][3];
        }
        ls0 += __shfl_xor_sync(0xffffffffu, ls0, 1);
        ls0 += __shfl_xor_sync(0xffffffffu, ls0, 2);
        ls1 += __shfl_xor_sync(0xffffffffu, ls1, 1);
        ls1 += __shfl_xor_sync(0xffffffffu, ls1, 2);
        l0v = l0v * sf0 + ls0;
        l1v = l1v * sf1 + ls1;
#pragma unroll
        for (int nt = 0; nt < 16; nt++) {
            o[nt][0] *= sf0; o[nt][1] *= sf0;
            o[nt][2] *= sf1; o[nt][3] *= sf1;
        }

        uint32_t ph[4][4];
#pragma unroll
        for (int k2 = 0; k2 < 4; k2++) {
            ph[k2][0] = cvt_plain_h(s[2*k2][0],   s[2*k2][1]);
            ph[k2][1] = cvt_plain_h(s[2*k2][2],   s[2*k2][3]);
            ph[k2][2] = cvt_plain_h(s[2*k2+1][0], s[2*k2+1][1]);
            ph[k2][3] = cvt_plain_h(s[2*k2+1][2], s[2*k2+1][3]);
        }

        // O += P V  (V already resident in this buffer)
#pragma unroll
        for (int k2 = 0; k2 < 4; k2++) {
#pragma unroll
            for (int npp = 0; npp < 4; npp++) {
                const int np0 = 2 * npp, np1 = 2 * npp + 1;
                uint32_t vh0[4], vh1[4];
                uint32_t va0 = vb + (k2 * 16 + v_row) * FL_STRIDE_B
                             + (np0 * 16 + v_coff) * 2;
                uint32_t va1 = va0 + 32;
                LDMT4(vh0[0], vh0[1], vh0[2], vh0[3], va0);
                LDMT4(vh1[0], vh1[1], vh1[2], vh1[3], va1);
                MMA16816(o[2*np0],   ph[k2], vh0[0], vh0[1]);
                MMA16816(o[2*np0+1], ph[k2], vh0[2], vh0[3]);
                MMA16816(o[2*np1],   ph[k2], vh1[0], vh1[1]);
                MMA16816(o[2*np1+1], ph[k2], vh1[2], vh1[3]);
            }
        }

        __syncthreads();    // all reads of buf(kt&1) complete before reuse

        // prefetch tile kt+2 into the buffer just freed
        if (kt + 2 <= qt) {
            const size_t ko = bho + (size_t)(kt + 2) * 64 * HDIM;
            const uint32_t kd = sb + (uint32_t)(1 + 2 * (kt & 1)) * FL_TILE;
#pragma unroll
            for (int i = 0; i < 8; i++) {
                int c = tid + i * 128;
                int r = c >> 4, sg = c & 15;
                uint32_t dof = (uint32_t)(r * FL_STRIDE_B + sg * 16);
                size_t so = ko + r * HDIM + sg * 8;
                CP16(kd + dof, (const char*)(Kp + so));
                CP16(kd + FL_TILE + dof, (const char*)(Vp + so));
            }
        }
        CPCOMMIT();         // uniform group count (empty near the tail)
    }

    const float inv0 = 1.0f / l0v, inv1 = 1.0f / l1v;
    const int b = bh >> 4, h = bh & 15;
    const int gr0 = q0 + w * 16 + (lane >> 2);
    const size_t ro0 = (size_t)(b * SEQ + gr0) * EMB + h * HDIM;
    const size_t ro1 = (size_t)(b * SEQ + gr0 + 8) * EMB + h * HDIM;
#pragma unroll
    for (int nt = 0; nt < 16; nt++) {
        const int col = nt * 8 + (lane & 3) * 2;
        *(uint32_t*)(ctx + ro0 + col) = cvt_plain_h(o[nt][0] * inv0, o[nt][1] * inv0);
        *(uint32_t*)(ctx + ro1 + col) = cvt_plain_h(o[nt][2] * inv1, o[nt][3] * inv1);
    }
}

// ---------------------------------------------------------------------------
extern "C" void kernel_launch(void* const* d_in, const int* in_sizes, int n_in,
                              void* d_out, int out_size)
{
    const float* x      = (const float*)d_in[0];
    const float* wqkv_w = (const float*)d_in[1];
    const float* wqkv_b = (const float*)d_in[2];
    const float* out_w  = (const float*)d_in[3];
    const float* out_b  = (const float*)d_in[4];
    float* out = (float*)d_out;

    __half *x16, *w16, *o16w;
    __half *qp, *kp, *vp, *c16;
    float* rope;
    cudaGetSymbolAddress((void**)&x16, g_x16);
    cudaGetSymbolAddress((void**)&w16, g_w16);
    cudaGetSymbolAddress((void**)&o16w, g_o16w);
    cudaGetSymbolAddress((void**)&qp, g_qp);
    cudaGetSymbolAddress((void**)&kp, g_kp);
    cudaGetSymbolAddress((void**)&vp, g_vp);
    cudaGetSymbolAddress((void**)&c16, g_c16);
    cudaGetSymbolAddress((void**)&rope, g_rope);

    cudaFuncSetAttribute(gemm_fp16, cudaFuncAttributeMaxDynamicSharedMemorySize, GEMM_SMEM);
    cudaFuncSetAttribute(gemm_qkv, cudaFuncAttributeMaxDynamicSharedMemorySize, GEMM_SMEM);
    cudaFuncSetAttribute(flash_mma, cudaFuncAttributeMaxDynamicSharedMemorySize, FLASH_SMEM);

    int n4;
    n4 = MROWS * EMB / 4;
    cvt_f32_h<<<(n4 + 255) / 256, 256>>>((const float4*)x, (uint2*)x16, n4);
    n4 = THREE_E * EMB / 4;
    cvt_f32_h<<<(n4 + 255) / 256, 256>>>((const float4*)wqkv_w, (uint2*)w16, n4);
    n4 = EMB * EMB / 4;
    cvt_f32_h<<<(n4 + 255) / 256, 256>>>((const float4*)out_w, (uint2*)o16w, n4);
    rope_table<<<(SEQ * 64 + 255) / 256, 256>>>(rope);

    // QKV projection with fused RoPE epilogue
    dim3 g1(THREE_E / 128, MROWS / 128);
    gemm_qkv<<<g1, 256, GEMM_SMEM>>>(x16, w16, wqkv_b, rope, qp, kp, vp, EMB);

    // attention (double-buffered KV)
    dim3 g2(SEQ / 64, NBH);
    flash_mma<<<g2, 128, FLASH_SMEM>>>(qp, kp, vp, c16);

    // output projection
    dim3 g3(EMB / 128, MROWS / 128);
    gemm_fp16<<<g3, 256, GEMM_SMEM>>>(c16, o16w, out_b, out, EMB, EMB);
}

// round 17
// speedup vs baseline: 1.1840x; 1.0080x over previous
#include <cuda_runtime.h>
#include <cuda_fp16.h>
#include <math.h>
#include <stdint.h>

#define BATCH 2
#define SEQ   2048
#define EMB   2048
#define HEADS 16
#define HDIM  128
#define THREE_E 6144
#define MROWS (BATCH*SEQ)     // 4096
#define NBH   (BATCH*HEADS)   // 32

// ---------------- scratch (__device__ globals; no cudaMalloc) ----------------
__device__ __half g_x16[(size_t)MROWS * EMB];                    // x plain fp16
__device__ __half g_w16[(size_t)THREE_E * EMB];                  // wqkv plain fp16
__device__ __half g_o16w[(size_t)EMB * EMB];                     // out_w plain fp16
__device__ __half g_qp[(size_t)NBH*SEQ*HDIM];                    // Q plain fp16
__device__ __half g_kp[(size_t)NBH*SEQ*HDIM];                    // K plain fp16
__device__ __half g_vp[(size_t)NBH*SEQ*HDIM];                    // V plain fp16
__device__ __half g_c16[(size_t)MROWS * EMB];                    // ctx plain fp16
__device__ float  g_rope[(size_t)SEQ * 64 * 2];                  // (cos,sin) table

// ---------------- PTX helpers ----------------
__device__ __forceinline__ uint32_t smem_u32(const void* p) {
    uint32_t a;
    asm("{ .reg .u64 t; cvta.to.shared.u64 t, %1; cvt.u32.u64 %0, t; }"
        : "=r"(a) : "l"(p));
    return a;
}
__device__ __forceinline__ uint32_t cvt_plain_h(float f0, float f1) {
    uint32_t h;
    asm("cvt.rn.f16x2.f32 %0, %1, %2;" : "=r"(h) : "f"(f1), "f"(f0));
    return h;
}
#define LDMX4(r0, r1, r2, r3, addr) \
    asm volatile("ldmatrix.sync.aligned.m8n8.x4.shared.b16 {%0,%1,%2,%3}, [%4];" \
        : "=r"(r0), "=r"(r1), "=r"(r2), "=r"(r3) : "r"(addr))
#define LDMT4(r0, r1, r2, r3, addr) \
    asm volatile("ldmatrix.sync.aligned.m8n8.x4.trans.shared.b16 {%0,%1,%2,%3}, [%4];" \
        : "=r"(r0), "=r"(r1), "=r"(r2), "=r"(r3) : "r"(addr))
#define MMA16816(d, a, b0, b1) \
    asm volatile("mma.sync.aligned.m16n8k16.row.col.f32.f16.f16.f32 " \
        "{%0,%1,%2,%3}, {%4,%5,%6,%7}, {%8,%9}, {%0,%1,%2,%3};" \
        : "+f"((d)[0]), "+f"((d)[1]), "+f"((d)[2]), "+f"((d)[3]) \
        : "r"((a)[0]), "r"((a)[1]), "r"((a)[2]), "r"((a)[3]), "r"(b0), "r"(b1))
#define CP16(dst, src) \
    asm volatile("cp.async.cg.shared.global [%0], [%1], 16;" :: "r"(dst), "l"(src))
#define CPCOMMIT() asm volatile("cp.async.commit_group;" ::: "memory")
#define CPWAIT0()  asm volatile("cp.async.wait_group 0;" ::: "memory")
#define CPWAIT1()  asm volatile("cp.async.wait_group 1;" ::: "memory")

// ---------------------------------------------------------------------------
// Prep: fp32 -> plain fp16 ; RoPE table
// ---------------------------------------------------------------------------
__global__ void cvt_f32_h(const float4* __restrict__ in,
                          uint2* __restrict__ o16, int n4)
{
    int i = blockIdx.x * blockDim.x + threadIdx.x;
    if (i >= n4) return;
    float4 v = in[i];
    o16[i] = make_uint2(cvt_plain_h(v.x, v.y), cvt_plain_h(v.z, v.w));
}

__global__ void rope_table(float* __restrict__ tab)
{
    int idx = blockIdx.x * blockDim.x + threadIdx.x;   // SEQ*64
    if (idx >= SEQ * 64) return;
    int j = idx & 63, s = idx >> 6;
    float inv = powf(10000.0f, -(float)j / 64.0f);
    float sn, cs;
    sincosf((float)s * inv, &sn, &cs);
    tab[idx * 2]     = cs;
    tab[idx * 2 + 1] = sn;
}

// ---------------------------------------------------------------------------
// Shared GEMM mainloop config: BM=BN=128, BK=64, 256 thr, 3-stage, 2 CTAs/SM
// ---------------------------------------------------------------------------
#define LDS 72                       // 64 fp16 data + 8 pad per row (144 B)
#define A_SB (128 * LDS * 2)         // 18432 B
#define STAGE_SB (2 * A_SB)          // 36864 B (A + B)
#define GEMM_SMEM (3 * STAGE_SB)     // 110592 B  -> 2 CTAs/SM

__device__ __forceinline__ void gemm_issue(
    const __half* A, const __half* B,
    uint32_t sbase, int m0, int n0, int K, int cc, int tid)
{
    const uint32_t stg = sbase + (uint32_t)(cc % 3) * STAGE_SB;
    const int k0 = cc * 64;
#pragma unroll
    for (int i = 0; i < 4; i++) {
        int c = tid + i * 256;       // 0..1023
        int r = c >> 3, sg = c & 7;
        uint32_t dof = (uint32_t)(r * 144 + sg * 16);
        size_t ao = (size_t)(m0 + r) * K + k0 + sg * 8;
        size_t bo = (size_t)(n0 + r) * K + k0 + sg * 8;
        CP16(stg + dof, (const char*)(A + ao));
        CP16(stg + A_SB + dof, (const char*)(B + bo));
    }
    CPCOMMIT();
}

__device__ __forceinline__ void gemm_mainloop(
    const __half* A, const __half* B, const uint32_t sbase,
    int m0, int n0, int K, int tid, int lane, int wm, int wn,
    float acc[4][4][4])
{
    const int NCH = K >> 6;
    gemm_issue(A, B, sbase, m0, n0, K, 0, tid);
    gemm_issue(A, B, sbase, m0, n0, K, 1, tid);

    const uint32_t a_row  = (uint32_t)(wm * 64 + (lane & 15));
    const uint32_t a_koff = (uint32_t)((lane >> 4) * 8);
    const uint32_t b_row  = (uint32_t)(wn * 32 + (lane & 7) + ((lane >> 4) << 3));
    const uint32_t b_koff = (uint32_t)(((lane >> 3) & 1) * 8);

    for (int c = 0; c < NCH; c++) {
        CPWAIT1();
        __syncthreads();
        if (c + 2 < NCH) gemm_issue(A, B, sbase, m0, n0, K, c + 2, tid);
        else CPCOMMIT();

        const uint32_t stg = sbase + (uint32_t)(c % 3) * STAGE_SB;
#pragma unroll
        for (int ks = 0; ks < 4; ks++) {
            const uint32_t kofs = (uint32_t)(ks * 16);
            uint32_t a[4][4];
#pragma unroll
            for (int mt = 0; mt < 4; mt++) {
                uint32_t adr = stg + ((a_row + mt * 16) * LDS + kofs + a_koff) * 2;
                LDMX4(a[mt][0], a[mt][1], a[mt][2], a[mt][3], adr);
            }
            uint32_t b[2][4];
#pragma unroll
            for (int p = 0; p < 2; p++) {
                uint32_t adr = stg + A_SB
                             + ((b_row + p * 16) * LDS + kofs + b_koff) * 2;
                LDMX4(b[p][0], b[p][1], b[p][2], b[p][3], adr);
            }
#pragma unroll
            for (int mt = 0; mt < 4; mt++)
#pragma unroll
                for (int nt = 0; nt < 4; nt++) {
                    const int p = nt >> 1, hh = (nt & 1) * 2;
                    MMA16816(acc[mt][nt], a[mt], b[p][hh], b[p][hh + 1]);
                }
        }
    }
}

// ---------------------------------------------------------------------------
// Out-projection GEMM: writes fp32 C + bias
// ---------------------------------------------------------------------------
__global__ __launch_bounds__(256, 2) void gemm_fp16(
    const __half* __restrict__ A, const __half* __restrict__ B,
    const float* __restrict__ bias, float* __restrict__ C, int N, int K)
{
    extern __shared__ char dsm[];
    __shared__ float sBias[128];

    const int tid  = threadIdx.x;
    const int lane = tid & 31;
    const int wid  = tid >> 5;
    const int wm   = wid >> 2;
    const int wn   = wid & 3;
    const int m0 = blockIdx.y * 128, n0 = blockIdx.x * 128;
    const uint32_t sbase = smem_u32(dsm);

    if (tid < 128) sBias[tid] = bias[n0 + tid];

    float acc[4][4][4];
#pragma unroll
    for (int mt = 0; mt < 4; mt++)
#pragma unroll
        for (int nt = 0; nt < 4; nt++)
#pragma unroll
            for (int r = 0; r < 4; r++) acc[mt][nt][r] = 0.0f;

    gemm_mainloop(A, B, sbase, m0, n0, K, tid, lane, wm, wn, acc);

    const int erow = wm * 64 + (lane >> 2);
    const int ecol = wn * 32 + (lane & 3) * 2;
#pragma unroll
    for (int mt = 0; mt < 4; mt++) {
#pragma unroll
        for (int nt = 0; nt < 4; nt++) {
            const int cc = ecol + nt * 8;
            const float b0 = sBias[cc], b1 = sBias[cc + 1];
            float* p0 = C + (size_t)(m0 + erow + mt * 16) * N + n0 + cc;
            float* p1 = C + (size_t)(m0 + erow + mt * 16 + 8) * N + n0 + cc;
            float2 v0 = {acc[mt][nt][0] + b0, acc[mt][nt][1] + b1};
            float2 v1 = {acc[mt][nt][2] + b0, acc[mt][nt][3] + b1};
            *(float2*)p0 = v0;
            *(float2*)p1 = v1;
        }
    }
}

// ---------------------------------------------------------------------------
// QKV GEMM with fused RoPE/scale epilogue (table trig). Q/K/V all plain fp16.
// N-tile (128 cols) = one (slot, head): slot = bx/16, head = bx%16.
// ---------------------------------------------------------------------------
#define CT_STRIDE 132   // fp32 stage-tile row stride

__global__ __launch_bounds__(256, 2) void gemm_qkv(
    const __half* __restrict__ A, const __half* __restrict__ B,
    const float* __restrict__ bias, const float* __restrict__ rope,
    __half* __restrict__ Qp, __half* __restrict__ Kp,
    __half* __restrict__ Vp, int K)
{
    extern __shared__ char dsm[];
    __shared__ float sBias[128];

    const int tid  = threadIdx.x;
    const int lane = tid & 31;
    const int wid  = tid >> 5;
    const int wm   = wid >> 2;
    const int wn   = wid & 3;
    const int m0 = blockIdx.y * 128, n0 = blockIdx.x * 128;
    const uint32_t sbase = smem_u32(dsm);

    if (tid < 128) sBias[tid] = bias[n0 + tid];

    float acc[4][4][4];
#pragma unroll
    for (int mt = 0; mt < 4; mt++)
#pragma unroll
        for (int nt = 0; nt < 4; nt++)
#pragma unroll
            for (int r = 0; r < 4; r++) acc[mt][nt][r] = 0.0f;

    gemm_mainloop(A, B, sbase, m0, n0, K, tid, lane, wm, wn, acc);

    // ---- stage acc + bias into smem fp32 tile (reuse pipeline smem) ----
    __syncthreads();
    float* ctile = (float*)dsm;
    const int erow = wm * 64 + (lane >> 2);
    const int ecol = wn * 32 + (lane & 3) * 2;
#pragma unroll
    for (int mt = 0; mt < 4; mt++) {
#pragma unroll
        for (int nt = 0; nt < 4; nt++) {
            const int cc = ecol + nt * 8;
            const float b0 = sBias[cc], b1 = sBias[cc + 1];
            ctile[(erow + mt * 16) * CT_STRIDE + cc]     = acc[mt][nt][0] + b0;
            ctile[(erow + mt * 16) * CT_STRIDE + cc + 1] = acc[mt][nt][1] + b1;
            ctile[(erow + mt * 16 + 8) * CT_STRIDE + cc]     = acc[mt][nt][2] + b0;
            ctile[(erow + mt * 16 + 8) * CT_STRIDE + cc + 1] = acc[mt][nt][3] + b1;
        }
    }
    __syncthreads();

    // ---- RoPE / store (trig from table) ----
    const int slot = blockIdx.x >> 4;      // 0=Q, 1=K, 2=V
    const int h    = blockIdx.x & 15;
    const float scale = 0.08838834764831845f;

#pragma unroll 4
    for (int i = 0; i < 32; i++) {
        int idx = tid + i * 256;           // 0..8191
        int r = idx >> 6, j = idx & 63;
        int row = m0 + r;
        int b = row >> 11;                 // / SEQ
        int s = row & (SEQ - 1);
        size_t dst = ((size_t)(b * HEADS + h) * SEQ + s) * HDIM + j;
        float v1 = ctile[r * CT_STRIDE + j];
        float v2 = ctile[r * CT_STRIDE + j + 64];
        if (slot == 2) {
            Vp[dst]      = __float2half_rn(v1);
            Vp[dst + 64] = __float2half_rn(v2);
        } else {
            float2 cssn = *(const float2*)(rope + (size_t)(s * 64 + j) * 2);
            float r1 = v1 * cssn.x - v2 * cssn.y;
            float r2 = v1 * cssn.y + v2 * cssn.x;
            if (slot == 0) {
                Qp[dst]      = __float2half_rn(r1 * scale);
                Qp[dst + 64] = __float2half_rn(r2 * scale);
            } else {
                Kp[dst]      = __float2half_rn(r1);
                Kp[dst + 64] = __float2half_rn(r2);
            }
        }
    }
}

// ---------------------------------------------------------------------------
// Flash attention: Q/K/V plain fp16, causal. KV tiles 128 wide (halved tile
// count). 128 threads (4 warps x 16 q-rows), BM=64, D=128, 2 CTAs/SM.
// smem: Q (64 rows), K (128 rows), V (128 rows)
// ---------------------------------------------------------------------------
#define FL_STRIDE_B 272                  // 136 fp16 per smem row
#define FL_TILE64  (64  * FL_STRIDE_B)   // 17408 B
#define FL_TILE128 (128 * FL_STRIDE_B)   // 34816 B
#define FLASH_SMEM (FL_TILE64 + 2 * FL_TILE128)  // 87040 B -> 2 CTAs/SM

__global__ __launch_bounds__(128, 2) void flash_mma(
    const __half* __restrict__ Qp, const __half* __restrict__ Kp,
    const __half* __restrict__ Vp,
    __half* __restrict__ ctx)
{
    extern __shared__ char fsm[];
    const int qt = gridDim.x - 1 - blockIdx.x;   // heavy tiles first
    const int bh = blockIdx.y;
    const int tid = threadIdx.x, lane = tid & 31, w = tid >> 5;
    const int q0 = qt * 64;
    const uint32_t sb = smem_u32(fsm);
    const uint32_t kbb = sb + FL_TILE64;
    const uint32_t vbb = kbb + FL_TILE128;

    // Load Q tile (regular stores; visible after first barrier)
    {
        const size_t qo = ((size_t)bh * SEQ + q0) * HDIM;
#pragma unroll
        for (int i = 0; i < 8; i++) {
            int c = tid + i * 128;
            int r = c >> 4, sg = c & 15;
            *(uint4*)(fsm + r * FL_STRIDE_B + sg * 16) =
                *(const uint4*)(Qp + qo + r * HDIM + sg * 8);
        }
    }

    float m0v = -1e30f, m1v = -1e30f, l0v = 0.0f, l1v = 0.0f;
    float o[16][4];
#pragma unroll
    for (int nt = 0; nt < 16; nt++)
#pragma unroll
        for (int r = 0; r < 4; r++) o[nt][r] = 0.0f;

    const uint32_t a_row  = (uint32_t)(w * 16 + (lane & 15));
    const uint32_t a_koff = (uint32_t)((lane >> 4) * 8);
    const uint32_t b_row  = (uint32_t)((lane & 7) + ((lane >> 4) << 3));
    const uint32_t b_koff = (uint32_t)(((lane >> 3) & 1) * 8);
    const uint32_t v_row  = (uint32_t)(lane & 15);
    const uint32_t v_coff = (uint32_t)((lane >> 4) * 8);

    const size_t bho = (size_t)bh * SEQ * HDIM;
    const int nkt = (qt >> 1) + 1;     // 128-wide kv tiles

    for (int kt = 0; kt < nkt; kt++) {
        __syncthreads();   // prev tile fully consumed (and Q stores on iter 0)

        const size_t ko = bho + (size_t)kt * 128 * HDIM;
        // K tile: 128 rows x 16 segs = 2048 uint4 -> 16 iters
#pragma unroll
        for (int i = 0; i < 16; i++) {
            int c = tid + i * 128;
            int r = c >> 4, sg = c & 15;
            uint32_t dof = (uint32_t)(r * FL_STRIDE_B + sg * 16);
            size_t so = ko + r * HDIM + sg * 8;
            CP16(kbb + dof, (const char*)(Kp + so));
        }
        CPCOMMIT();
#pragma unroll
        for (int i = 0; i < 16; i++) {
            int c = tid + i * 128;
            int r = c >> 4, sg = c & 15;
            uint32_t dof = (uint32_t)(r * FL_STRIDE_B + sg * 16);
            size_t so = ko + r * HDIM + sg * 8;
            CP16(vbb + dof, (const char*)(Vp + so));
        }
        CPCOMMIT();

        CPWAIT1();         // K resident
        __syncthreads();

        // ---- S = Q K^T over 128 kv cols ----
        float s[16][4];
#pragma unroll
        for (int nt = 0; nt < 16; nt++)
#pragma unroll
            for (int r = 0; r < 4; r++) s[nt][r] = 0.0f;

#pragma unroll
        for (int ks = 0; ks < 8; ks++) {
            uint32_t q[4];
            uint32_t qadr = sb + a_row * FL_STRIDE_B + (ks * 16 + a_koff) * 2;
            LDMX4(q[0], q[1], q[2], q[3], qadr);
            uint32_t kf[8][4];
#pragma unroll
            for (int np = 0; np < 8; np++) {
                uint32_t kadr = kbb + (np * 16 + b_row) * FL_STRIDE_B
                              + (ks * 16 + b_koff) * 2;
                LDMX4(kf[np][0], kf[np][1], kf[np][2], kf[np][3], kadr);
            }
#pragma unroll
            for (int np = 0; np < 8; np++) {
                MMA16816(s[2*np],   q, kf[np][0], kf[np][1]);
                MMA16816(s[2*np+1], q, kf[np][2], kf[np][3]);
            }
        }

        // causal mask on diagonal tile
        if (kt == (qt >> 1)) {
            const int r0 = q0 + w * 16 + (lane >> 2);
            const int r1 = r0 + 8;
            const int c0 = kt * 128;
#pragma unroll
            for (int nt = 0; nt < 16; nt++) {
                const int cb = c0 + nt * 8 + (lane & 3) * 2;
                if (cb     > r0) s[nt][0] = -1e30f;
                if (cb + 1 > r0) s[nt][1] = -1e30f;
                if (cb     > r1) s[nt][2] = -1e30f;
                if (cb + 1 > r1) s[nt][3] = -1e30f;
            }
        }

        float mx0 = -1e30f, mx1 = -1e30f;
#pragma unroll
        for (int nt = 0; nt < 16; nt++) {
            mx0 = fmaxf(mx0, fmaxf(s[nt][0], s[nt][1]));
            mx1 = fmaxf(mx1, fmaxf(s[nt][2], s[nt][3]));
        }
        mx0 = fmaxf(mx0, __shfl_xor_sync(0xffffffffu, mx0, 1));
        mx0 = fmaxf(mx0, __shfl_xor_sync(0xffffffffu, mx0, 2));
        mx1 = fmaxf(mx1, __shfl_xor_sync(0xffffffffu, mx1, 1));
        mx1 = fmaxf(mx1, __shfl_xor_sync(0xffffffffu, mx1, 2));

        float mn0 = fmaxf(m0v, mx0), mn1 = fmaxf(m1v, mx1);
        float sf0 = __expf(m0v - mn0), sf1 = __expf(m1v - mn1);
        m0v = mn0; m1v = mn1;

        float ls0 = 0.0f, ls1 = 0.0f;
#pragma unroll
        for (int nt = 0; nt < 16; nt++) {
            s[nt][0] = __expf(s[nt][0] - mn0); ls0 += s[nt][0];
            s[nt][1] = __expf(s[nt][1] - mn0); ls0 += s[nt][1];
            s[nt][2] = __expf(s[nt][2] - mn1); ls1 += s[nt][2];
            s[nt][3] = __expf(s[nt][3] - mn1); ls1 += s[nt][3];
        }
        ls0 += __shfl_xor_sync(0xffffffffu, ls0, 1);
        ls0 += __shfl_xor_sync(0xffffffffu, ls0, 2);
        ls1 += __shfl_xor_sync(0xffffffffu, ls1, 1);
        ls1 += __shfl_xor_sync(0xffffffffu, ls1, 2);
        l0v = l0v * sf0 + ls0;
        l1v = l1v * sf1 + ls1;
#pragma unroll
        for (int nt = 0; nt < 16; nt++) {
            o[nt][0] *= sf0; o[nt][1] *= sf0;
            o[nt][2] *= sf1; o[nt][3] *= sf1;
        }

        // P fragments (plain fp16): 8 k-groups of 16 kv rows
        uint32_t ph[8][4];
#pragma unroll
        for (int k2 = 0; k2 < 8; k2++) {
            ph[k2][0] = cvt_plain_h(s[2*k2][0],   s[2*k2][1]);
            ph[k2][1] = cvt_plain_h(s[2*k2][2],   s[2*k2][3]);
            ph[k2][2] = cvt_plain_h(s[2*k2+1][0], s[2*k2+1][1]);
            ph[k2][3] = cvt_plain_h(s[2*k2+1][2], s[2*k2+1][3]);
        }

        CPWAIT0();         // V resident
        __syncthreads();

        // O += P V over 128 kv rows
#pragma unroll
        for (int k2 = 0; k2 < 8; k2++) {
#pragma unroll
            for (int npp = 0; npp < 4; npp++) {
                const int np0 = 2 * npp, np1 = 2 * npp + 1;
                uint32_t vh0[4], vh1[4];
                uint32_t va0 = vbb + (k2 * 16 + v_row) * FL_STRIDE_B
                             + (np0 * 16 + v_coff) * 2;
                uint32_t va1 = va0 + 32;
                LDMT4(vh0[0], vh0[1], vh0[2], vh0[3], va0);
                LDMT4(vh1[0], vh1[1], vh1[2], vh1[3], va1);
                MMA16816(o[2*np0],   ph[k2], vh0[0], vh0[1]);
                MMA16816(o[2*np0+1], ph[k2], vh0[2], vh0[3]);
                MMA16816(o[2*np1],   ph[k2], vh1[0], vh1[1]);
                MMA16816(o[2*np1+1], ph[k2], vh1[2], vh1[3]);
            }
        }
    }

    const float inv0 = 1.0f / l0v, inv1 = 1.0f / l1v;
    const int b = bh >> 4, h = bh & 15;
    const int gr0 = q0 + w * 16 + (lane >> 2);
    const size_t ro0 = (size_t)(b * SEQ + gr0) * EMB + h * HDIM;
    const size_t ro1 = (size_t)(b * SEQ + gr0 + 8) * EMB + h * HDIM;
#pragma unroll
    for (int nt = 0; nt < 16; nt++) {
        const int col = nt * 8 + (lane & 3) * 2;
        *(uint32_t*)(ctx + ro0 + col) = cvt_plain_h(o[nt][0] * inv0, o[nt][1] * inv0);
        *(uint32_t*)(ctx + ro1 + col) = cvt_plain_h(o[nt][2] * inv1, o[nt][3] * inv1);
    }
}

// ---------------------------------------------------------------------------
extern "C" void kernel_launch(void* const* d_in, const int* in_sizes, int n_in,
                              void* d_out, int out_size)
{
    const float* x      = (const float*)d_in[0];
    const float* wqkv_w = (const float*)d_in[1];
    const float* wqkv_b = (const float*)d_in[2];
    const float* out_w  = (const float*)d_in[3];
    const float* out_b  = (const float*)d_in[4];
    float* out = (float*)d_out;

    __half *x16, *w16, *o16w;
    __half *qp, *kp, *vp, *c16;
    float* rope;
    cudaGetSymbolAddress((void**)&x16, g_x16);
    cudaGetSymbolAddress((void**)&w16, g_w16);
    cudaGetSymbolAddress((void**)&o16w, g_o16w);
    cudaGetSymbolAddress((void**)&qp, g_qp);
    cudaGetSymbolAddress((void**)&kp, g_kp);
    cudaGetSymbolAddress((void**)&vp, g_vp);
    cudaGetSymbolAddress((void**)&c16, g_c16);
    cudaGetSymbolAddress((void**)&rope, g_rope);

    cudaFuncSetAttribute(gemm_fp16, cudaFuncAttributeMaxDynamicSharedMemorySize, GEMM_SMEM);
    cudaFuncSetAttribute(gemm_qkv, cudaFuncAttributeMaxDynamicSharedMemorySize, GEMM_SMEM);
    cudaFuncSetAttribute(flash_mma, cudaFuncAttributeMaxDynamicSharedMemorySize, FLASH_SMEM);

    int n4;
    n4 = MROWS * EMB / 4;
    cvt_f32_h<<<(n4 + 255) / 256, 256>>>((const float4*)x, (uint2*)x16, n4);
    n4 = THREE_E * EMB / 4;
    cvt_f32_h<<<(n4 + 255) / 256, 256>>>((const float4*)wqkv_w, (uint2*)w16, n4);
    n4 = EMB * EMB / 4;
    cvt_f32_h<<<(n4 + 255) / 256, 256>>>((const float4*)out_w, (uint2*)o16w, n4);
    rope_table<<<(SEQ * 64 + 255) / 256, 256>>>(rope);

    // QKV projection with fused RoPE epilogue
    dim3 g1(THREE_E / 128, MROWS / 128);
    gemm_qkv<<<g1, 256, GEMM_SMEM>>>(x16, w16, wqkv_b, rope, qp, kp, vp, EMB);

    // attention (128-wide KV tiles)
    dim3 g2(SEQ / 64, NBH);
    flash_mma<<<g2, 128, FLASH_SMEM>>>(qp, kp, vp, c16);

    // output projection
    dim3 g3(EMB / 128, MROWS / 128);
    gemm_fp16<<<g3, 256, GEMM_SMEM>>>(c16, o16w, out_b, out, EMB, EMB);
}